// round 2
// baseline (speedup 1.0000x reference)
#include <cuda_runtime.h>
#include <math.h>
#include <stdint.h>

// Problem constants
#define BB 2
#define TT 1024
#define DD 2048
#define HH 16
#define DHD 128          // head dim
#define RR (BB*TT)       // 2048 total rows
#define DHALF (DD/2)     // 1024
#define LCH 128          // EMA chunk length
#define NC (TT/LCH)      // 8 chunks
#define BD (BB*DD)       // 4096

// -------- device scratch (static; no allocations allowed) --------
__device__ float g_q[RR*DD];
__device__ float g_l2[RR*DD];
__device__ float g_hdn[RR*DHALF];
__device__ float g_fused[RR*DD];
__device__ float g_attno[RR*DD];
__device__ float g_fin[NC*BD];
__device__ float g_carry[NC*BD];
__device__ float g_scores[(size_t)BB*HH*TT*TT];   // 128 MB

// ================= EMA (chunked parallel scan) =================
// pass1: local EMA within each chunk of LCH steps; store locals + chunk finals
__global__ void ema_pass1(const float* __restrict__ x) {
    int idx = blockIdx.x * blockDim.x + threadIdx.x;  // BB*NC*DD = 32768
    int d = idx % DD;
    int c = (idx / DD) % NC;
    int b = idx / (DD * NC);
    const float beta = 0.9f, om = 1.0f - 0.9f;
    size_t base = ((size_t)b * TT + (size_t)c * LCH) * DD + d;
    float s = 0.f;
    #pragma unroll 4
    for (int p = 0; p < LCH; p++) {
        s = beta * s + om * x[base + (size_t)p * DD];
        g_l2[base + (size_t)p * DD] = s;
    }
    g_fin[c * BD + b * DD + d] = s;
}

// pass2: combine chunk carries: S_c = fin_{c-1} + beta^L * S_{c-1}, S_0 = 0
__global__ void ema_pass2() {
    int idx = blockIdx.x * blockDim.x + threadIdx.x;  // BD = 4096
    const float bl = __powf(0.9f, (float)LCH);
    float P = 0.f;
    g_carry[idx] = 0.f;
    for (int c = 1; c < NC; c++) {
        P = g_fin[(c - 1) * BD + idx] + bl * P;
        g_carry[c * BD + idx] = P;
    }
}

// ================= generic tiled SGEMM, C = A * B^T =================
// A: M x K row-major (lda), Bm: N x K row-major (ldb).
// MODE 0: plain store    MODE 1: bias + silu    MODE 2: scatter to [b,h,t,dh]
template<int MODE>
__global__ void __launch_bounds__(256, 2)
sgemm_nt(const float* __restrict__ A, const float* __restrict__ Bm,
         float* __restrict__ C, int M, int N, int K,
         int lda, int ldb, int ldc, const float* __restrict__ bias) {
    __shared__ float As[16][128];
    __shared__ float Bs[16][128];
    int tid = threadIdx.x;
    int m0 = blockIdx.y * 128, n0 = blockIdx.x * 128;
    int lr = tid >> 2;           // 0..63
    int lc = (tid & 3) << 2;     // 0,4,8,12
    float acc[8][8];
    #pragma unroll
    for (int i = 0; i < 8; i++)
        #pragma unroll
        for (int j = 0; j < 8; j++) acc[i][j] = 0.f;

    const float* Ap = A + (size_t)m0 * lda;
    const float* Bp = Bm + (size_t)n0 * ldb;
    int tx = tid & 15, ty = tid >> 4;

    for (int k0 = 0; k0 < K; k0 += 16) {
        #pragma unroll
        for (int i = 0; i < 2; i++) {
            int row = lr + i * 64;
            float4 va = *(const float4*)(Ap + (size_t)row * lda + k0 + lc);
            As[lc + 0][row] = va.x; As[lc + 1][row] = va.y;
            As[lc + 2][row] = va.z; As[lc + 3][row] = va.w;
            float4 vb = *(const float4*)(Bp + (size_t)row * ldb + k0 + lc);
            Bs[lc + 0][row] = vb.x; Bs[lc + 1][row] = vb.y;
            Bs[lc + 2][row] = vb.z; Bs[lc + 3][row] = vb.w;
        }
        __syncthreads();
        #pragma unroll
        for (int kk = 0; kk < 16; kk++) {
            float a[8], bb[8];
            *(float4*)(a)     = *(const float4*)&As[kk][ty * 8];
            *(float4*)(a + 4) = *(const float4*)&As[kk][ty * 8 + 4];
            *(float4*)(bb)     = *(const float4*)&Bs[kk][tx * 8];
            *(float4*)(bb + 4) = *(const float4*)&Bs[kk][tx * 8 + 4];
            #pragma unroll
            for (int i = 0; i < 8; i++)
                #pragma unroll
                for (int j = 0; j < 8; j++)
                    acc[i][j] = fmaf(a[i], bb[j], acc[i][j]);
        }
        __syncthreads();
    }

    #pragma unroll
    for (int i = 0; i < 8; i++) {
        int row = m0 + ty * 8 + i;
        #pragma unroll
        for (int j = 0; j < 8; j++) {
            int col = n0 + tx * 8 + j;
            float v = acc[i][j];
            if (MODE == 0) {
                C[(size_t)row * ldc + col] = v;
            } else if (MODE == 1) {
                v += bias[col];
                v = v / (1.f + expf(-v));          // silu
                C[(size_t)row * ldc + col] = v;
            } else {  // MODE 2: scatter into [b,h,t,dh]
                int b = row / TT, t = row % TT;
                int h = col / DHD, jj = col % DHD;
                C[(((size_t)(b * HH + h)) * TT + t) * DHD + jj] = v;
            }
        }
    }
}

// ================= router (softmax over 3) + level fusion =================
__global__ void router_fuse(const float* __restrict__ x,
                            const float* __restrict__ l3mem,
                            const float* __restrict__ rw2,
                            const float* __restrict__ rb2,
                            float* __restrict__ lam_out) {
    int r = blockIdx.x;          // 0..RR-1
    int tid = threadIdx.x;       // 256
    int b = r / TT, t = r % TT;
    const float* hrow = g_hdn + (size_t)r * DHALF;

    float p0 = 0.f, p1 = 0.f, p2 = 0.f;
    for (int j = tid; j < DHALF; j += 256) {
        float h = hrow[j];
        p0 = fmaf(h, rw2[j], p0);
        p1 = fmaf(h, rw2[DHALF + j], p1);
        p2 = fmaf(h, rw2[2 * DHALF + j], p2);
    }
    #pragma unroll
    for (int o = 16; o; o >>= 1) {
        p0 += __shfl_xor_sync(0xffffffffu, p0, o);
        p1 += __shfl_xor_sync(0xffffffffu, p1, o);
        p2 += __shfl_xor_sync(0xffffffffu, p2, o);
    }
    __shared__ float red0[8], red1[8], red2[8];
    __shared__ float lam[3];
    int lane = tid & 31, w = tid >> 5;
    if (lane == 0) { red0[w] = p0; red1[w] = p1; red2[w] = p2; }
    __syncthreads();
    if (tid == 0) {
        float l0 = rb2[0], l1 = rb2[1], l2v = rb2[2];
        #pragma unroll
        for (int ww = 0; ww < 8; ww++) { l0 += red0[ww]; l1 += red1[ww]; l2v += red2[ww]; }
        float mx = fmaxf(l0, fmaxf(l1, l2v));
        float e0 = expf(l0 - mx), e1 = expf(l1 - mx), e2 = expf(l2v - mx);
        float inv = 1.f / (e0 + e1 + e2);
        lam[0] = e0 * inv; lam[1] = e1 * inv; lam[2] = e2 * inv;
        lam_out[r * 3 + 0] = lam[0];
        lam_out[r * 3 + 1] = lam[1];
        lam_out[r * 3 + 2] = lam[2];
    }
    __syncthreads();
    float la = lam[0], lb = lam[1], lcc = lam[2];

    int c = t / LCH, p = t % LCH;
    float pb = __powf(0.9f, (float)(p + 1));   // beta^(p+1) for carry injection
    const float* carr = g_carry + c * BD + b * DD;
    size_t ro = (size_t)r * DD;
    for (int j = tid; j < DD; j += 256) {
        float l2v = g_l2[ro + j] + pb * carr[j];
        g_fused[ro + j] = la * x[ro + j] + lb * l2v + lcc * l3mem[b * DD + j];
    }
}

// ================= scores = scale * qh @ kh^T (causal-skipped) =================
__global__ void __launch_bounds__(256, 2)
scores_gemm(const float* __restrict__ kh) {
    int z = blockIdx.z;               // b*H + h
    int m0 = blockIdx.y * 128, n0 = blockIdx.x * 128;
    if (n0 > m0 + 127) return;        // fully masked block
    int b = z / HH, h = z % HH;
    const float* A  = g_q + (size_t)b * TT * DD + (size_t)h * DHD;  // lda = DD
    const float* Bp = kh + (size_t)z * TT * DHD;                     // ldb = DHD
    float* C = g_scores + (size_t)z * TT * TT;                       // ldc = TT

    __shared__ float As[16][128];
    __shared__ float Bs[16][128];
    int tid = threadIdx.x;
    int lr = tid >> 2, lc = (tid & 3) << 2;
    int tx = tid & 15, ty = tid >> 4;
    float acc[8][8];
    #pragma unroll
    for (int i = 0; i < 8; i++)
        #pragma unroll
        for (int j = 0; j < 8; j++) acc[i][j] = 0.f;

    for (int k0 = 0; k0 < DHD; k0 += 16) {
        #pragma unroll
        for (int i = 0; i < 2; i++) {
            int row = lr + i * 64;
            float4 va = *(const float4*)(A + (size_t)(m0 + row) * DD + k0 + lc);
            As[lc + 0][row] = va.x; As[lc + 1][row] = va.y;
            As[lc + 2][row] = va.z; As[lc + 3][row] = va.w;
            float4 vb = *(const float4*)(Bp + (size_t)(n0 + row) * DHD + k0 + lc);
            Bs[lc + 0][row] = vb.x; Bs[lc + 1][row] = vb.y;
            Bs[lc + 2][row] = vb.z; Bs[lc + 3][row] = vb.w;
        }
        __syncthreads();
        #pragma unroll
        for (int kk = 0; kk < 16; kk++) {
            float a[8], bb[8];
            *(float4*)(a)     = *(const float4*)&As[kk][ty * 8];
            *(float4*)(a + 4) = *(const float4*)&As[kk][ty * 8 + 4];
            *(float4*)(bb)     = *(const float4*)&Bs[kk][tx * 8];
            *(float4*)(bb + 4) = *(const float4*)&Bs[kk][tx * 8 + 4];
            #pragma unroll
            for (int i = 0; i < 8; i++)
                #pragma unroll
                for (int j = 0; j < 8; j++)
                    acc[i][j] = fmaf(a[i], bb[j], acc[i][j]);
        }
        __syncthreads();
    }
    const float scale = 0.08838834764831845f;   // 1/sqrt(128)
    #pragma unroll
    for (int i = 0; i < 8; i++) {
        int row = m0 + ty * 8 + i;
        #pragma unroll
        for (int j = 0; j < 8; j++) {
            int col = n0 + tx * 8 + j;
            C[(size_t)row * TT + col] = (col <= row) ? acc[i][j] * scale : -1e30f;
        }
    }
}

// ================= causal row softmax (in place, zero-fill j>i) =================
__global__ void softmax_rows() {
    int g = blockIdx.x;                 // z*T + i  (32768 blocks)
    int z = g / TT, i = g % TT;
    float* row = g_scores + (size_t)z * TT * TT + (size_t)i * TT;
    int n = i + 1;
    int tid = threadIdx.x;
    __shared__ float sbuf[8];

    float mx = -3.4e38f;
    for (int j = tid; j < n; j += 256) mx = fmaxf(mx, row[j]);
    #pragma unroll
    for (int o = 16; o; o >>= 1) mx = fmaxf(mx, __shfl_xor_sync(0xffffffffu, mx, o));
    if ((tid & 31) == 0) sbuf[tid >> 5] = mx;
    __syncthreads();
    float M = -3.4e38f;
    #pragma unroll
    for (int ww = 0; ww < 8; ww++) M = fmaxf(M, sbuf[ww]);
    __syncthreads();

    float sum = 0.f;
    for (int j = tid; j < n; j += 256) {
        float e = expf(row[j] - M);
        row[j] = e;
        sum += e;
    }
    #pragma unroll
    for (int o = 16; o; o >>= 1) sum += __shfl_xor_sync(0xffffffffu, sum, o);
    if ((tid & 31) == 0) sbuf[tid >> 5] = sum;
    __syncthreads();
    float S = 0.f;
    #pragma unroll
    for (int ww = 0; ww < 8; ww++) S += sbuf[ww];
    float inv = 1.f / S;
    for (int j = tid; j < n; j += 256) row[j] *= inv;
    for (int j = n + tid; j < TT; j += 256) row[j] = 0.f;
}

// ================= O = P @ V (NN gemm, causal K truncation) =================
__global__ void __launch_bounds__(256, 2)
pv_gemm(const float* __restrict__ vh) {
    int z = blockIdx.z;                 // b*H + h
    int m0 = blockIdx.y * 128;          // N = 128: single x block
    int b = z / HH, h = z % HH;
    const float* A  = g_scores + (size_t)z * TT * TT;  // lda = TT
    const float* Bp = vh + (size_t)z * TT * DHD;       // [K=T rows][N=128], ldb = DHD

    __shared__ float As[16][128];
    __shared__ float Bs[16][128];
    int tid = threadIdx.x;
    int lr = tid >> 2, lc = (tid & 3) << 2;
    int tx = tid & 15, ty = tid >> 4;
    float acc[8][8];
    #pragma unroll
    for (int i = 0; i < 8; i++)
        #pragma unroll
        for (int j = 0; j < 8; j++) acc[i][j] = 0.f;

    int kmax = m0 + 128;                // rows beyond block's max i are all zero in P
    for (int k0 = 0; k0 < kmax; k0 += 16) {
        #pragma unroll
        for (int i = 0; i < 2; i++) {
            int row = lr + i * 64;
            float4 va = *(const float4*)(A + (size_t)(m0 + row) * TT + k0 + lc);
            As[lc + 0][row] = va.x; As[lc + 1][row] = va.y;
            As[lc + 2][row] = va.z; As[lc + 3][row] = va.w;
        }
        #pragma unroll
        for (int i = 0; i < 2; i++) {
            int kr = (tid >> 5) + i * 8;         // 0..15
            int c4 = (tid & 31) * 4;             // 0..124
            float4 vb = *(const float4*)(Bp + (size_t)(k0 + kr) * DHD + c4);
            *(float4*)&Bs[kr][c4] = vb;
        }
        __syncthreads();
        #pragma unroll
        for (int kk = 0; kk < 16; kk++) {
            float a[8], bb[8];
            *(float4*)(a)     = *(const float4*)&As[kk][ty * 8];
            *(float4*)(a + 4) = *(const float4*)&As[kk][ty * 8 + 4];
            *(float4*)(bb)     = *(const float4*)&Bs[kk][tx * 8];
            *(float4*)(bb + 4) = *(const float4*)&Bs[kk][tx * 8 + 4];
            #pragma unroll
            for (int i = 0; i < 8; i++)
                #pragma unroll
                for (int j = 0; j < 8; j++)
                    acc[i][j] = fmaf(a[i], bb[j], acc[i][j]);
        }
        __syncthreads();
    }
    #pragma unroll
    for (int i = 0; i < 8; i++) {
        int row = m0 + ty * 8 + i;               // t index
        #pragma unroll
        for (int j = 0; j < 8; j++) {
            int col = tx * 8 + j;                // dh index
            g_attno[((size_t)b * TT + row) * DD + h * DHD + col] = acc[i][j];
        }
    }
}

// ================= launch =================
extern "C" void kernel_launch(void* const* d_in, const int* in_sizes, int n_in,
                              void* d_out, int out_size) {
    (void)in_sizes; (void)n_in; (void)out_size;
    const float* x    = (const float*)d_in[0];
    const float* l3m  = (const float*)d_in[1];
    const float* wq   = (const float*)d_in[2];
    const float* wk   = (const float*)d_in[3];
    const float* wv   = (const float*)d_in[4];
    const float* wo   = (const float*)d_in[5];
    const float* rw1  = (const float*)d_in[6];
    const float* rb1  = (const float*)d_in[7];
    const float* rw2  = (const float*)d_in[8];
    const float* rb2  = (const float*)d_in[9];

    float* out     = (float*)d_out;                 // [b,t,d]
    float* kh_out  = out + (size_t)RR * DD;         // [b,h,t,dh]
    float* vh_out  = kh_out + (size_t)RR * DD;      // [b,h,t,dh]
    float* lam_out = vh_out + (size_t)RR * DD;      // [b,t,3]

    float *q_, *hdn_, *fused_, *attno_;
    cudaGetSymbolAddress((void**)&q_,     g_q);
    cudaGetSymbolAddress((void**)&hdn_,   g_hdn);
    cudaGetSymbolAddress((void**)&fused_, g_fused);
    cudaGetSymbolAddress((void**)&attno_, g_attno);

    // EMA scan (chunked)
    ema_pass1<<<BB * NC * DD / 256, 256>>>(x);
    ema_pass2<<<BD / 256, 256>>>();

    // q = x @ wq^T
    sgemm_nt<0><<<dim3(DD / 128, RR / 128), 256>>>(x, wq, q_, RR, DD, DD, DD, DD, DD, nullptr);
    // hdn = silu(q @ rw1^T + rb1)
    sgemm_nt<1><<<dim3(DHALF / 128, RR / 128), 256>>>(q_, rw1, hdn_, RR, DHALF, DD, DD, DD, DHALF, rb1);
    // router softmax + fused levels
    router_fuse<<<RR, 256>>>(x, l3m, rw2, rb2, lam_out);
    // kh / vh (scattered into head-major output layout)
    sgemm_nt<2><<<dim3(DD / 128, RR / 128), 256>>>(fused_, wk, kh_out, RR, DD, DD, DD, DD, 0, nullptr);
    sgemm_nt<2><<<dim3(DD / 128, RR / 128), 256>>>(fused_, wv, vh_out, RR, DD, DD, DD, DD, 0, nullptr);
    // attention
    scores_gemm<<<dim3(TT / 128, TT / 128, BB * HH), 256>>>(kh_out);
    softmax_rows<<<BB * HH * TT, 256>>>();
    pv_gemm<<<dim3(1, TT / 128, BB * HH), 256>>>(vh_out);
    // out = attno @ wo^T
    sgemm_nt<0><<<dim3(DD / 128, RR / 128), 256>>>(attno_, wo, out, RR, DD, DD, DD, DD, DD, nullptr);
}

// round 4
// speedup vs baseline: 2.2160x; 2.2160x over previous
#include <cuda_runtime.h>
#include <cuda_bf16.h>
#include <math.h>
#include <stdint.h>

// Problem constants
#define BB 2
#define TT 1024
#define DD 2048
#define HH 16
#define DHD 128
#define RR (BB*TT)       // 2048
#define DHALF (DD/2)     // 1024
#define LCH 128
#define NC (TT/LCH)
#define BD (BB*DD)

#define KDIM 2048
#define NCHUNK (KDIM/64)         // 32 chunks of 64 bf16
#define STAGE_BYTES 65536        // 4 tiles x 16KB (Ahi, Alo, Bhi, Blo)
#define SMEM_DYN (2*STAGE_BYTES + 1024)

// -------- fp32 scratch --------
__device__ float g_q[RR*DD];
__device__ float g_l2[RR*DD];
__device__ float g_hdn[RR*DHALF];
__device__ float g_fused[RR*DD];
__device__ float g_attno[RR*DD];
__device__ float g_fin[NC*BD];
__device__ float g_carry[NC*BD];
__device__ float g_scores[(size_t)BB*HH*TT*TT];   // 128 MB

// -------- bf16 hi/lo scratch --------
__device__ __nv_bfloat16 g_xhi[RR*DD],  g_xlo[RR*DD];
__device__ __nv_bfloat16 g_qhi[RR*DD],  g_qlo[RR*DD];
__device__ __nv_bfloat16 g_fhi[RR*DD],  g_flo[RR*DD];
__device__ __nv_bfloat16 g_ahi[RR*DD],  g_alo[RR*DD];
__device__ __nv_bfloat16 g_wqhi[DD*DD], g_wqlo[DD*DD];
__device__ __nv_bfloat16 g_wkhi[DD*DD], g_wklo[DD*DD];
__device__ __nv_bfloat16 g_wvhi[DD*DD], g_wvlo[DD*DD];
__device__ __nv_bfloat16 g_wohi[DD*DD], g_wolo[DD*DD];
__device__ __nv_bfloat16 g_r1hi[DHALF*DD], g_r1lo[DHALF*DD];

// ================= PTX helpers (all sm_80-era: valid on plain sm_103) ======
__device__ __forceinline__ uint32_t smem_u32(const void* p) {
    uint32_t a;
    asm("{ .reg .u64 t; cvta.to.shared.u64 t, %1; cvt.u32.u64 %0, t; }" : "=r"(a) : "l"(p));
    return a;
}
__device__ __forceinline__ void cpasync16(uint32_t s, const void* g) {
    asm volatile("cp.async.cg.shared.global [%0], [%1], 16;" :: "r"(s), "l"(g));
}
#define CP_COMMIT() asm volatile("cp.async.commit_group;" ::: "memory")
#define CP_WAIT(n)  asm volatile("cp.async.wait_group %0;" :: "n"(n) : "memory")

__device__ __forceinline__ void ldsm4(uint32_t* r, uint32_t addr) {
    asm volatile("ldmatrix.sync.aligned.m8n8.x4.shared.b16 {%0,%1,%2,%3}, [%4];"
        : "=r"(r[0]), "=r"(r[1]), "=r"(r[2]), "=r"(r[3]) : "r"(addr));
}
__device__ __forceinline__ void mma16816(float* c, const uint32_t* a, const uint32_t* b) {
    asm volatile(
        "mma.sync.aligned.m16n8k16.row.col.f32.bf16.bf16.f32 "
        "{%0,%1,%2,%3}, {%4,%5,%6,%7}, {%8,%9}, {%0,%1,%2,%3};"
        : "+f"(c[0]), "+f"(c[1]), "+f"(c[2]), "+f"(c[3])
        : "r"(a[0]), "r"(a[1]), "r"(a[2]), "r"(a[3]), "r"(b[0]), "r"(b[1]));
}

// ================= fp32 -> bf16 hi/lo split =================
__global__ void cvt_split(const float4* __restrict__ src,
                          __nv_bfloat162* __restrict__ hi,
                          __nv_bfloat162* __restrict__ lo, int n4) {
    int i = blockIdx.x * blockDim.x + threadIdx.x;
    if (i >= n4) return;
    float4 v = src[i];
    __nv_bfloat16 h0 = __float2bfloat16(v.x), h1 = __float2bfloat16(v.y);
    __nv_bfloat16 h2 = __float2bfloat16(v.z), h3 = __float2bfloat16(v.w);
    __nv_bfloat16 l0 = __float2bfloat16(v.x - __bfloat162float(h0));
    __nv_bfloat16 l1 = __float2bfloat16(v.y - __bfloat162float(h1));
    __nv_bfloat16 l2 = __float2bfloat16(v.z - __bfloat162float(h2));
    __nv_bfloat16 l3 = __float2bfloat16(v.w - __bfloat162float(h3));
    hi[2*i]   = __nv_bfloat162(h0, h1);
    hi[2*i+1] = __nv_bfloat162(h2, h3);
    lo[2*i]   = __nv_bfloat162(l0, l1);
    lo[2*i+1] = __nv_bfloat162(l2, l3);
}

// ================= HMMA GEMM: C = A * B^T  (split bf16, fp32 acc) ==========
// A: M x 2048 hi/lo, B: N x 2048 hi/lo (both row-major, K contiguous).
// CTA tile 128x128, 256 threads = 8 warps (4 in M x 2 in N), warp tile 32x64.
// BK = 64 bf16 (128B rows, SW128 swizzle), 2-stage cp.async pipeline.
// MODE 0: plain   MODE 1: bias+silu   MODE 2: scatter [b,h,t,dh]
template<int MODE>
__global__ void __launch_bounds__(256, 1)
gemm_mma(const __nv_bfloat16* __restrict__ Ahi, const __nv_bfloat16* __restrict__ Alo,
         const __nv_bfloat16* __restrict__ Bhi, const __nv_bfloat16* __restrict__ Blo,
         float* __restrict__ C, int ldc, const float* __restrict__ bias) {
    extern __shared__ char dsm[];
    const int tid  = threadIdx.x;
    const int wid  = tid >> 5, lane = tid & 31;
    const int m0   = blockIdx.y * 128, n0 = blockIdx.x * 128;
    const int wm   = (wid & 3) * 32;       // warp row offset in tile
    const int wn   = (wid >> 2) * 64;      // warp col offset in tile
    uint32_t sb = (smem_u32(dsm) + 1023u) & ~1023u;

    // ---- cp.async stage loader: 4 tiles of 128 rows x 128B, SW128 swizzle
    const __nv_bfloat16* gsrc[4] = {
        Ahi + (size_t)m0 * KDIM, Alo + (size_t)m0 * KDIM,
        Bhi + (size_t)n0 * KDIM, Blo + (size_t)n0 * KDIM };

    auto load_stage = [&](int s, int k0) {
        uint32_t base = sb + (uint32_t)s * STAGE_BYTES;
        #pragma unroll
        for (int tI = 0; tI < 4; tI++) {
            uint32_t tb = base + (uint32_t)tI * 16384u;
            const char* g = (const char*)(gsrc[tI] + k0);
            #pragma unroll
            for (int it = 0; it < 4; it++) {
                int idx = tid + it * 256;      // 0..1023
                int m = idx >> 3, j = idx & 7;
                uint32_t saddr = tb + (uint32_t)m * 128u + (uint32_t)((j ^ (m & 7)) << 4);
                cpasync16(saddr, g + (size_t)m * (KDIM * 2) + j * 16);
            }
        }
        CP_COMMIT();
    };

    float acc[2][8][4];
    #pragma unroll
    for (int i = 0; i < 2; i++)
        #pragma unroll
        for (int j = 0; j < 8; j++)
            #pragma unroll
            for (int r = 0; r < 4; r++) acc[i][j][r] = 0.f;

    // ldmatrix per-lane row/khalf decomposition
    const int aRow0 = wm + ((lane >> 3) & 1) * 8 + (lane & 7);   // + mt*16
    const int aKh   = (lane >> 4) & 1;
    const int bRow0 = wn + ((lane >> 4) & 1) * 8 + (lane & 7);   // + g*16
    const int bKh   = (lane >> 3) & 1;

    load_stage(0, 0);
    load_stage(1, 64);

    #pragma unroll 1
    for (int c = 0; c < NCHUNK; c++) {
        if (c + 2 < NCHUNK) { CP_WAIT(1); } else { CP_WAIT(0); }
        __syncthreads();

        uint32_t base = sb + (uint32_t)(c & 1) * STAGE_BYTES;
        #pragma unroll
        for (int kk = 0; kk < 4; kk++) {
            uint32_t ah[2][4], al[2][4], bh[4][4], bl[4][4];
            #pragma unroll
            for (int mt = 0; mt < 2; mt++) {
                int row = aRow0 + mt * 16;
                int cc = (kk * 2 + aKh) ^ (row & 7);
                uint32_t off = (uint32_t)row * 128u + (uint32_t)cc * 16u;
                ldsm4(ah[mt], base + off);
                ldsm4(al[mt], base + 16384u + off);
            }
            #pragma unroll
            for (int g = 0; g < 4; g++) {
                int row = bRow0 + g * 16;
                int cc = (kk * 2 + bKh) ^ (row & 7);
                uint32_t off = (uint32_t)row * 128u + (uint32_t)cc * 16u;
                ldsm4(bh[g], base + 32768u + off);
                ldsm4(bl[g], base + 49152u + off);
            }
            #pragma unroll
            for (int i = 0; i < 2; i++)
                #pragma unroll
                for (int j = 0; j < 8; j++) {
                    const uint32_t* bph = &bh[j >> 1][(j & 1) * 2];
                    const uint32_t* bpl = &bl[j >> 1][(j & 1) * 2];
                    mma16816(acc[i][j], ah[i], bph);
                    mma16816(acc[i][j], ah[i], bpl);
                    mma16816(acc[i][j], al[i], bph);
                }
        }
        __syncthreads();
        if (c + 2 < NCHUNK) load_stage(c & 1, (c + 2) * 64);
    }

    // ---- epilogue
    #pragma unroll
    for (int i = 0; i < 2; i++) {
        #pragma unroll
        for (int j = 0; j < 8; j++) {
            #pragma unroll
            for (int r = 0; r < 4; r++) {
                int row = m0 + wm + i * 16 + (lane >> 2) + (r >> 1) * 8;
                int col = n0 + wn + j * 8 + (lane & 3) * 2 + (r & 1);
                float v = acc[i][j][r];
                if (MODE == 0) {
                    C[(size_t)row * ldc + col] = v;
                } else if (MODE == 1) {
                    v += bias[col];
                    v = v / (1.f + expf(-v));
                    C[(size_t)row * ldc + col] = v;
                } else {
                    int b = row >> 10, t = row & 1023;
                    int h = col >> 7,  jj = col & 127;
                    C[(((size_t)(b * HH + h)) * TT + t) * DHD + jj] = v;
                }
            }
        }
    }
}

// ================= EMA (chunked parallel scan) =================
__global__ void ema_pass1(const float* __restrict__ x) {
    int idx = blockIdx.x * blockDim.x + threadIdx.x;
    int d = idx % DD;
    int c = (idx / DD) % NC;
    int b = idx / (DD * NC);
    const float beta = 0.9f, om = 1.0f - 0.9f;
    size_t base = ((size_t)b * TT + (size_t)c * LCH) * DD + d;
    float s = 0.f;
    #pragma unroll 4
    for (int p = 0; p < LCH; p++) {
        s = beta * s + om * x[base + (size_t)p * DD];
        g_l2[base + (size_t)p * DD] = s;
    }
    g_fin[c * BD + b * DD + d] = s;
}
__global__ void ema_pass2() {
    int idx = blockIdx.x * blockDim.x + threadIdx.x;
    const float bl = __powf(0.9f, (float)LCH);
    float P = 0.f;
    g_carry[idx] = 0.f;
    for (int c = 1; c < NC; c++) {
        P = g_fin[(c - 1) * BD + idx] + bl * P;
        g_carry[c * BD + idx] = P;
    }
}

// ================= router + level fusion =================
__global__ void router_fuse(const float* __restrict__ x,
                            const float* __restrict__ l3mem,
                            const float* __restrict__ rw2,
                            const float* __restrict__ rb2,
                            float* __restrict__ lam_out) {
    int r = blockIdx.x;
    int tid = threadIdx.x;
    int b = r / TT, t = r % TT;
    const float* hrow = g_hdn + (size_t)r * DHALF;

    float p0 = 0.f, p1 = 0.f, p2 = 0.f;
    for (int j = tid; j < DHALF; j += 256) {
        float h = hrow[j];
        p0 = fmaf(h, rw2[j], p0);
        p1 = fmaf(h, rw2[DHALF + j], p1);
        p2 = fmaf(h, rw2[2 * DHALF + j], p2);
    }
    #pragma unroll
    for (int o = 16; o; o >>= 1) {
        p0 += __shfl_xor_sync(0xffffffffu, p0, o);
        p1 += __shfl_xor_sync(0xffffffffu, p1, o);
        p2 += __shfl_xor_sync(0xffffffffu, p2, o);
    }
    __shared__ float red0[8], red1[8], red2[8];
    __shared__ float lam[3];
    int lane = tid & 31, w = tid >> 5;
    if (lane == 0) { red0[w] = p0; red1[w] = p1; red2[w] = p2; }
    __syncthreads();
    if (tid == 0) {
        float l0 = rb2[0], l1 = rb2[1], l2v = rb2[2];
        #pragma unroll
        for (int ww = 0; ww < 8; ww++) { l0 += red0[ww]; l1 += red1[ww]; l2v += red2[ww]; }
        float mx = fmaxf(l0, fmaxf(l1, l2v));
        float e0 = expf(l0 - mx), e1 = expf(l1 - mx), e2 = expf(l2v - mx);
        float inv = 1.f / (e0 + e1 + e2);
        lam[0] = e0 * inv; lam[1] = e1 * inv; lam[2] = e2 * inv;
        lam_out[r * 3 + 0] = lam[0];
        lam_out[r * 3 + 1] = lam[1];
        lam_out[r * 3 + 2] = lam[2];
    }
    __syncthreads();
    float la = lam[0], lb = lam[1], lcc = lam[2];

    int c = t / LCH, p = t % LCH;
    float pb = __powf(0.9f, (float)(p + 1));
    const float* carr = g_carry + c * BD + b * DD;
    size_t ro = (size_t)r * DD;
    for (int j = tid; j < DD; j += 256) {
        float l2v = g_l2[ro + j] + pb * carr[j];
        g_fused[ro + j] = la * x[ro + j] + lb * l2v + lcc * l3mem[b * DD + j];
    }
}

// ================= scores = scale * qh @ kh^T (causal-skipped) =============
__global__ void __launch_bounds__(256, 2)
scores_gemm(const float* __restrict__ kh) {
    int z = blockIdx.z;
    int m0 = blockIdx.y * 128, n0 = blockIdx.x * 128;
    if (n0 > m0 + 127) return;
    int b = z / HH, h = z % HH;
    const float* A  = g_q + (size_t)b * TT * DD + (size_t)h * DHD;
    const float* Bp = kh + (size_t)z * TT * DHD;
    float* C = g_scores + (size_t)z * TT * TT;

    __shared__ float As[16][128];
    __shared__ float Bs[16][128];
    int tid = threadIdx.x;
    int lr = tid >> 2, lc = (tid & 3) << 2;
    int tx = tid & 15, ty = tid >> 4;
    float acc[8][8];
    #pragma unroll
    for (int i = 0; i < 8; i++)
        #pragma unroll
        for (int j = 0; j < 8; j++) acc[i][j] = 0.f;

    for (int k0 = 0; k0 < DHD; k0 += 16) {
        #pragma unroll
        for (int i = 0; i < 2; i++) {
            int row = lr + i * 64;
            float4 va = *(const float4*)(A + (size_t)(m0 + row) * DD + k0 + lc);
            As[lc + 0][row] = va.x; As[lc + 1][row] = va.y;
            As[lc + 2][row] = va.z; As[lc + 3][row] = va.w;
            float4 vb = *(const float4*)(Bp + (size_t)(n0 + row) * DHD + k0 + lc);
            Bs[lc + 0][row] = vb.x; Bs[lc + 1][row] = vb.y;
            Bs[lc + 2][row] = vb.z; Bs[lc + 3][row] = vb.w;
        }
        __syncthreads();
        #pragma unroll
        for (int kk = 0; kk < 16; kk++) {
            float a[8], bb[8];
            *(float4*)(a)     = *(const float4*)&As[kk][ty * 8];
            *(float4*)(a + 4) = *(const float4*)&As[kk][ty * 8 + 4];
            *(float4*)(bb)     = *(const float4*)&Bs[kk][tx * 8];
            *(float4*)(bb + 4) = *(const float4*)&Bs[kk][tx * 8 + 4];
            #pragma unroll
            for (int i = 0; i < 8; i++)
                #pragma unroll
                for (int j = 0; j < 8; j++)
                    acc[i][j] = fmaf(a[i], bb[j], acc[i][j]);
        }
        __syncthreads();
    }
    const float scale = 0.08838834764831845f;
    #pragma unroll
    for (int i = 0; i < 8; i++) {
        int row = m0 + ty * 8 + i;
        #pragma unroll
        for (int j = 0; j < 8; j++) {
            int col = n0 + tx * 8 + j;
            C[(size_t)row * TT + col] = (col <= row) ? acc[i][j] * scale : -1e30f;
        }
    }
}

// ================= causal row softmax =================
__global__ void softmax_rows() {
    int g = blockIdx.x;
    int z = g / TT, i = g % TT;
    float* row = g_scores + (size_t)z * TT * TT + (size_t)i * TT;
    int n = i + 1;
    int tid = threadIdx.x;
    __shared__ float sbuf[8];

    float mx = -3.4e38f;
    for (int j = tid; j < n; j += 256) mx = fmaxf(mx, row[j]);
    #pragma unroll
    for (int o = 16; o; o >>= 1) mx = fmaxf(mx, __shfl_xor_sync(0xffffffffu, mx, o));
    if ((tid & 31) == 0) sbuf[tid >> 5] = mx;
    __syncthreads();
    float M = -3.4e38f;
    #pragma unroll
    for (int ww = 0; ww < 8; ww++) M = fmaxf(M, sbuf[ww]);
    __syncthreads();

    float sum = 0.f;
    for (int j = tid; j < n; j += 256) {
        float e = expf(row[j] - M);
        row[j] = e;
        sum += e;
    }
    #pragma unroll
    for (int o = 16; o; o >>= 1) sum += __shfl_xor_sync(0xffffffffu, sum, o);
    if ((tid & 31) == 0) sbuf[tid >> 5] = sum;
    __syncthreads();
    float S = 0.f;
    #pragma unroll
    for (int ww = 0; ww < 8; ww++) S += sbuf[ww];
    float inv = 1.f / S;
    for (int j = tid; j < n; j += 256) row[j] *= inv;
    for (int j = n + tid; j < TT; j += 256) row[j] = 0.f;
}

// ================= O = P @ V =================
__global__ void __launch_bounds__(256, 2)
pv_gemm(const float* __restrict__ vh) {
    int z = blockIdx.z;
    int m0 = blockIdx.y * 128;
    int b = z / HH, h = z % HH;
    const float* A  = g_scores + (size_t)z * TT * TT;
    const float* Bp = vh + (size_t)z * TT * DHD;

    __shared__ float As[16][128];
    __shared__ float Bs[16][128];
    int tid = threadIdx.x;
    int lr = tid >> 2, lc = (tid & 3) << 2;
    int tx = tid & 15, ty = tid >> 4;
    float acc[8][8];
    #pragma unroll
    for (int i = 0; i < 8; i++)
        #pragma unroll
        for (int j = 0; j < 8; j++) acc[i][j] = 0.f;

    int kmax = m0 + 128;
    for (int k0 = 0; k0 < kmax; k0 += 16) {
        #pragma unroll
        for (int i = 0; i < 2; i++) {
            int row = lr + i * 64;
            float4 va = *(const float4*)(A + (size_t)(m0 + row) * TT + k0 + lc);
            As[lc + 0][row] = va.x; As[lc + 1][row] = va.y;
            As[lc + 2][row] = va.z; As[lc + 3][row] = va.w;
        }
        #pragma unroll
        for (int i = 0; i < 2; i++) {
            int kr = (tid >> 5) + i * 8;
            int c4 = (tid & 31) * 4;
            float4 vb = *(const float4*)(Bp + (size_t)(k0 + kr) * DHD + c4);
            *(float4*)&Bs[kr][c4] = vb;
        }
        __syncthreads();
        #pragma unroll
        for (int kk = 0; kk < 16; kk++) {
            float a[8], bb[8];
            *(float4*)(a)     = *(const float4*)&As[kk][ty * 8];
            *(float4*)(a + 4) = *(const float4*)&As[kk][ty * 8 + 4];
            *(float4*)(bb)     = *(const float4*)&Bs[kk][tx * 8];
            *(float4*)(bb + 4) = *(const float4*)&Bs[kk][tx * 8 + 4];
            #pragma unroll
            for (int i = 0; i < 8; i++)
                #pragma unroll
                for (int j = 0; j < 8; j++)
                    acc[i][j] = fmaf(a[i], bb[j], acc[i][j]);
        }
        __syncthreads();
    }
    #pragma unroll
    for (int i = 0; i < 8; i++) {
        int row = m0 + ty * 8 + i;
        #pragma unroll
        for (int j = 0; j < 8; j++) {
            int col = tx * 8 + j;
            g_attno[((size_t)b * TT + row) * DD + h * DHD + col] = acc[i][j];
        }
    }
}

// ================= launch =================
extern "C" void kernel_launch(void* const* d_in, const int* in_sizes, int n_in,
                              void* d_out, int out_size) {
    (void)in_sizes; (void)n_in; (void)out_size;
    const float* x    = (const float*)d_in[0];
    const float* l3m  = (const float*)d_in[1];
    const float* wq   = (const float*)d_in[2];
    const float* wk   = (const float*)d_in[3];
    const float* wv   = (const float*)d_in[4];
    const float* wo   = (const float*)d_in[5];
    const float* rw1  = (const float*)d_in[6];
    const float* rb1  = (const float*)d_in[7];
    const float* rw2  = (const float*)d_in[8];
    const float* rb2  = (const float*)d_in[9];

    float* out     = (float*)d_out;
    float* kh_out  = out + (size_t)RR * DD;
    float* vh_out  = kh_out + (size_t)RR * DD;
    float* lam_out = vh_out + (size_t)RR * DD;

    float *q_, *hdn_, *fused_, *attno_;
    cudaGetSymbolAddress((void**)&q_,     g_q);
    cudaGetSymbolAddress((void**)&hdn_,   g_hdn);
    cudaGetSymbolAddress((void**)&fused_, g_fused);
    cudaGetSymbolAddress((void**)&attno_, g_attno);

    __nv_bfloat16 *xhi,*xlo,*qhi,*qlo,*fhi,*flo,*ahi,*alo;
    __nv_bfloat16 *wqh,*wql,*wkh,*wkl,*wvh,*wvl,*woh,*wol,*r1h,*r1l;
    cudaGetSymbolAddress((void**)&xhi, g_xhi);  cudaGetSymbolAddress((void**)&xlo, g_xlo);
    cudaGetSymbolAddress((void**)&qhi, g_qhi);  cudaGetSymbolAddress((void**)&qlo, g_qlo);
    cudaGetSymbolAddress((void**)&fhi, g_fhi);  cudaGetSymbolAddress((void**)&flo, g_flo);
    cudaGetSymbolAddress((void**)&ahi, g_ahi);  cudaGetSymbolAddress((void**)&alo, g_alo);
    cudaGetSymbolAddress((void**)&wqh, g_wqhi); cudaGetSymbolAddress((void**)&wql, g_wqlo);
    cudaGetSymbolAddress((void**)&wkh, g_wkhi); cudaGetSymbolAddress((void**)&wkl, g_wklo);
    cudaGetSymbolAddress((void**)&wvh, g_wvhi); cudaGetSymbolAddress((void**)&wvl, g_wvlo);
    cudaGetSymbolAddress((void**)&woh, g_wohi); cudaGetSymbolAddress((void**)&wol, g_wolo);
    cudaGetSymbolAddress((void**)&r1h, g_r1hi); cudaGetSymbolAddress((void**)&r1l, g_r1lo);

    cudaFuncSetAttribute(gemm_mma<0>, cudaFuncAttributeMaxDynamicSharedMemorySize, SMEM_DYN);
    cudaFuncSetAttribute(gemm_mma<1>, cudaFuncAttributeMaxDynamicSharedMemorySize, SMEM_DYN);
    cudaFuncSetAttribute(gemm_mma<2>, cudaFuncAttributeMaxDynamicSharedMemorySize, SMEM_DYN);

    const int NBIG = RR * DD / 4;
    const int NR1  = DHALF * DD / 4;

    // hi/lo splits of inputs + weights
    cvt_split<<<NBIG/256, 256>>>((const float4*)x,  (__nv_bfloat162*)xhi, (__nv_bfloat162*)xlo, NBIG);
    cvt_split<<<NBIG/256, 256>>>((const float4*)wq, (__nv_bfloat162*)wqh, (__nv_bfloat162*)wql, NBIG);
    cvt_split<<<NBIG/256, 256>>>((const float4*)wk, (__nv_bfloat162*)wkh, (__nv_bfloat162*)wkl, NBIG);
    cvt_split<<<NBIG/256, 256>>>((const float4*)wv, (__nv_bfloat162*)wvh, (__nv_bfloat162*)wvl, NBIG);
    cvt_split<<<NBIG/256, 256>>>((const float4*)wo, (__nv_bfloat162*)woh, (__nv_bfloat162*)wol, NBIG);
    cvt_split<<<NR1/256,  256>>>((const float4*)rw1,(__nv_bfloat162*)r1h, (__nv_bfloat162*)r1l, NR1);

    // EMA scan
    ema_pass1<<<BB * NC * DD / 256, 256>>>(x);
    ema_pass2<<<BD / 256, 256>>>();

    // q = x @ wq^T (tensor cores, split bf16)
    gemm_mma<0><<<dim3(DD/128, RR/128), 256, SMEM_DYN>>>(xhi, xlo, wqh, wql, q_, DD, nullptr);
    cvt_split<<<NBIG/256, 256>>>((const float4*)q_, (__nv_bfloat162*)qhi, (__nv_bfloat162*)qlo, NBIG);
    // hdn = silu(q @ rw1^T + rb1)
    gemm_mma<1><<<dim3(DHALF/128, RR/128), 256, SMEM_DYN>>>(qhi, qlo, r1h, r1l, hdn_, DHALF, rb1);
    // router + fuse
    router_fuse<<<RR, 256>>>(x, l3m, rw2, rb2, lam_out);
    cvt_split<<<NBIG/256, 256>>>((const float4*)fused_, (__nv_bfloat162*)fhi, (__nv_bfloat162*)flo, NBIG);
    // kh / vh
    gemm_mma<2><<<dim3(DD/128, RR/128), 256, SMEM_DYN>>>(fhi, flo, wkh, wkl, kh_out, 0, nullptr);
    gemm_mma<2><<<dim3(DD/128, RR/128), 256, SMEM_DYN>>>(fhi, flo, wvh, wvl, vh_out, 0, nullptr);
    // attention (SIMT fp32)
    scores_gemm<<<dim3(TT/128, TT/128, BB*HH), 256>>>(kh_out);
    softmax_rows<<<BB*HH*TT, 256>>>();
    pv_gemm<<<dim3(1, TT/128, BB*HH), 256>>>(vh_out);
    // out = attno @ wo^T
    cvt_split<<<NBIG/256, 256>>>((const float4*)attno_, (__nv_bfloat162*)ahi, (__nv_bfloat162*)alo, NBIG);
    gemm_mma<0><<<dim3(DD/128, RR/128), 256, SMEM_DYN>>>(ahi, alo, woh, wol, out, DD, nullptr);
}

// round 5
// speedup vs baseline: 2.7096x; 1.2228x over previous
#include <cuda_runtime.h>
#include <cuda_bf16.h>
#include <math.h>
#include <stdint.h>

// Problem constants
#define BB 2
#define TT 1024
#define DD 2048
#define HH 16
#define DHD 128
#define RR (BB*TT)       // 2048
#define DHALF (DD/2)     // 1024
#define LCH 128
#define NC (TT/LCH)
#define BD (BB*DD)

#define KDIM 2048
#define NCHUNK (KDIM/64)
#define STAGE_BYTES 65536
#define SMEM_GEMM (2*STAGE_BYTES + 1024)
#define SMEM_SCORES (131072 + 1024)
#define SMEM_PV (65536 + 1024)

// -------- fp32 scratch --------
__device__ float g_hdn[RR*DHALF];
__device__ float g_l2[RR*DD];
__device__ float g_fin[NC*BD];
__device__ float g_carry[NC*BD];
__device__ float g_scores[(size_t)BB*HH*TT*TT];   // 128 MB

// -------- bf16 hi/lo scratch --------
__device__ __nv_bfloat16 g_xhi[RR*DD],  g_xlo[RR*DD];
__device__ __nv_bfloat16 g_qhi[RR*DD],  g_qlo[RR*DD];
__device__ __nv_bfloat16 g_fhi[RR*DD],  g_flo[RR*DD];
__device__ __nv_bfloat16 g_ahi[RR*DD],  g_alo[RR*DD];
__device__ __nv_bfloat16 g_khhi[RR*DD], g_khlo[RR*DD];   // [b,h,t,dh]
__device__ __nv_bfloat16 g_wqhi[DD*DD], g_wqlo[DD*DD];
__device__ __nv_bfloat16 g_wkhi[DD*DD], g_wklo[DD*DD];
__device__ __nv_bfloat16 g_wvhi[DD*DD], g_wvlo[DD*DD];
__device__ __nv_bfloat16 g_wohi[DD*DD], g_wolo[DD*DD];
__device__ __nv_bfloat16 g_r1hi[DHALF*DD], g_r1lo[DHALF*DD];

// ================= PTX helpers =================
__device__ __forceinline__ uint32_t smem_u32(const void* p) {
    uint32_t a;
    asm("{ .reg .u64 t; cvta.to.shared.u64 t, %1; cvt.u32.u64 %0, t; }" : "=r"(a) : "l"(p));
    return a;
}
__device__ __forceinline__ void cpasync16(uint32_t s, const void* g) {
    asm volatile("cp.async.cg.shared.global [%0], [%1], 16;" :: "r"(s), "l"(g));
}
#define CP_COMMIT() asm volatile("cp.async.commit_group;" ::: "memory")
#define CP_WAIT(n)  asm volatile("cp.async.wait_group %0;" :: "n"(n) : "memory")

__device__ __forceinline__ void ldsm4(uint32_t* r, uint32_t addr) {
    asm volatile("ldmatrix.sync.aligned.m8n8.x4.shared.b16 {%0,%1,%2,%3}, [%4];"
        : "=r"(r[0]), "=r"(r[1]), "=r"(r[2]), "=r"(r[3]) : "r"(addr));
}
__device__ __forceinline__ void ldsm4t(uint32_t* r, uint32_t addr) {
    asm volatile("ldmatrix.sync.aligned.m8n8.x4.trans.shared.b16 {%0,%1,%2,%3}, [%4];"
        : "=r"(r[0]), "=r"(r[1]), "=r"(r[2]), "=r"(r[3]) : "r"(addr));
}
__device__ __forceinline__ void mma16816(float* c, const uint32_t* a, const uint32_t* b) {
    asm volatile(
        "mma.sync.aligned.m16n8k16.row.col.f32.bf16.bf16.f32 "
        "{%0,%1,%2,%3}, {%4,%5,%6,%7}, {%8,%9}, {%0,%1,%2,%3};"
        : "+f"(c[0]), "+f"(c[1]), "+f"(c[2]), "+f"(c[3])
        : "r"(a[0]), "r"(a[1]), "r"(a[2]), "r"(a[3]), "r"(b[0]), "r"(b[1]));
}
// 8 floats -> 8 bf16 hi (4 b32) + 8 bf16 lo (4 b32), store v4 to smem
__device__ __forceinline__ void cvt8_sts(uint32_t sa_hi, uint32_t sa_lo,
                                         float4 v0, float4 v1) {
    float f[8] = {v0.x, v0.y, v0.z, v0.w, v1.x, v1.y, v1.z, v1.w};
    uint32_t ph[4], pl[4];
    #pragma unroll
    for (int i = 0; i < 4; i++) {
        __nv_bfloat16 h0 = __float2bfloat16(f[2*i]);
        __nv_bfloat16 h1 = __float2bfloat16(f[2*i+1]);
        __nv_bfloat16 l0 = __float2bfloat16(f[2*i]   - __bfloat162float(h0));
        __nv_bfloat16 l1 = __float2bfloat16(f[2*i+1] - __bfloat162float(h1));
        __nv_bfloat162 hp(h0, h1), lp(l0, l1);
        ph[i] = *(uint32_t*)&hp; pl[i] = *(uint32_t*)&lp;
    }
    asm volatile("st.shared.v4.b32 [%0], {%1,%2,%3,%4};"
                 :: "r"(sa_hi), "r"(ph[0]), "r"(ph[1]), "r"(ph[2]), "r"(ph[3]));
    asm volatile("st.shared.v4.b32 [%0], {%1,%2,%3,%4};"
                 :: "r"(sa_lo), "r"(pl[0]), "r"(pl[1]), "r"(pl[2]), "r"(pl[3]));
}

// ================= fp32 -> bf16 hi/lo split =================
__global__ void cvt_split(const float4* __restrict__ src,
                          __nv_bfloat162* __restrict__ hi,
                          __nv_bfloat162* __restrict__ lo, int n4) {
    int i = blockIdx.x * blockDim.x + threadIdx.x;
    if (i >= n4) return;
    float4 v = src[i];
    __nv_bfloat16 h0 = __float2bfloat16(v.x), h1 = __float2bfloat16(v.y);
    __nv_bfloat16 h2 = __float2bfloat16(v.z), h3 = __float2bfloat16(v.w);
    __nv_bfloat16 l0 = __float2bfloat16(v.x - __bfloat162float(h0));
    __nv_bfloat16 l1 = __float2bfloat16(v.y - __bfloat162float(h1));
    __nv_bfloat16 l2 = __float2bfloat16(v.z - __bfloat162float(h2));
    __nv_bfloat16 l3 = __float2bfloat16(v.w - __bfloat162float(h3));
    hi[2*i]   = __nv_bfloat162(h0, h1);
    hi[2*i+1] = __nv_bfloat162(h2, h3);
    lo[2*i]   = __nv_bfloat162(l0, l1);
    lo[2*i+1] = __nv_bfloat162(l2, l3);
}

// ================= HMMA GEMM: C = A * B^T (split bf16, fp32 acc) ===========
// MODE 0: fp32 plain   MODE 1: bias+silu fp32   MODE 2: fp32 scatter [b,h,t,dh]
// MODE 4: bf16 hi/lo plain   MODE 5: fp32 scatter + bf16 hi/lo scatter
template<int MODE>
__global__ void __launch_bounds__(256, 1)
gemm_mma(const __nv_bfloat16* __restrict__ Ahi, const __nv_bfloat16* __restrict__ Alo,
         const __nv_bfloat16* __restrict__ Bhi, const __nv_bfloat16* __restrict__ Blo,
         float* __restrict__ C, __nv_bfloat16* __restrict__ Chi,
         __nv_bfloat16* __restrict__ Clo, int ldc, const float* __restrict__ bias) {
    extern __shared__ char dsm[];
    const int tid  = threadIdx.x;
    const int wid  = tid >> 5, lane = tid & 31;
    const int m0   = blockIdx.y * 128, n0 = blockIdx.x * 128;
    const int wm   = (wid & 3) * 32;
    const int wn   = (wid >> 2) * 64;
    uint32_t sb = (smem_u32(dsm) + 1023u) & ~1023u;

    const __nv_bfloat16* gsrc[4] = {
        Ahi + (size_t)m0 * KDIM, Alo + (size_t)m0 * KDIM,
        Bhi + (size_t)n0 * KDIM, Blo + (size_t)n0 * KDIM };

    auto load_stage = [&](int s, int k0) {
        uint32_t base = sb + (uint32_t)s * STAGE_BYTES;
        #pragma unroll
        for (int tI = 0; tI < 4; tI++) {
            uint32_t tb = base + (uint32_t)tI * 16384u;
            const char* g = (const char*)(gsrc[tI] + k0);
            #pragma unroll
            for (int it = 0; it < 4; it++) {
                int idx = tid + it * 256;
                int m = idx >> 3, j = idx & 7;
                uint32_t saddr = tb + (uint32_t)m * 128u + (uint32_t)((j ^ (m & 7)) << 4);
                cpasync16(saddr, g + (size_t)m * (KDIM * 2) + j * 16);
            }
        }
        CP_COMMIT();
    };

    float acc[2][8][4];
    #pragma unroll
    for (int i = 0; i < 2; i++)
        #pragma unroll
        for (int j = 0; j < 8; j++)
            #pragma unroll
            for (int r = 0; r < 4; r++) acc[i][j][r] = 0.f;

    const int aRow0 = wm + ((lane >> 3) & 1) * 8 + (lane & 7);
    const int aKh   = (lane >> 4) & 1;
    const int bRow0 = wn + ((lane >> 4) & 1) * 8 + (lane & 7);
    const int bKh   = (lane >> 3) & 1;

    load_stage(0, 0);
    load_stage(1, 64);

    #pragma unroll 1
    for (int c = 0; c < NCHUNK; c++) {
        if (c + 2 < NCHUNK) { CP_WAIT(1); } else { CP_WAIT(0); }
        __syncthreads();

        uint32_t base = sb + (uint32_t)(c & 1) * STAGE_BYTES;
        #pragma unroll
        for (int kk = 0; kk < 4; kk++) {
            uint32_t ah[2][4], al[2][4], bh[4][4], bl[4][4];
            #pragma unroll
            for (int mt = 0; mt < 2; mt++) {
                int row = aRow0 + mt * 16;
                int cc = (kk * 2 + aKh) ^ (row & 7);
                uint32_t off = (uint32_t)row * 128u + (uint32_t)cc * 16u;
                ldsm4(ah[mt], base + off);
                ldsm4(al[mt], base + 16384u + off);
            }
            #pragma unroll
            for (int g = 0; g < 4; g++) {
                int row = bRow0 + g * 16;
                int cc = (kk * 2 + bKh) ^ (row & 7);
                uint32_t off = (uint32_t)row * 128u + (uint32_t)cc * 16u;
                ldsm4(bh[g], base + 32768u + off);
                ldsm4(bl[g], base + 49152u + off);
            }
            #pragma unroll
            for (int i = 0; i < 2; i++)
                #pragma unroll
                for (int j = 0; j < 8; j++) {
                    const uint32_t* bph = &bh[j >> 1][(j & 1) * 2];
                    const uint32_t* bpl = &bl[j >> 1][(j & 1) * 2];
                    mma16816(acc[i][j], ah[i], bph);
                    mma16816(acc[i][j], ah[i], bpl);
                    mma16816(acc[i][j], al[i], bph);
                }
        }
        __syncthreads();
        if (c + 2 < NCHUNK) load_stage(c & 1, (c + 2) * 64);
    }

    #pragma unroll
    for (int i = 0; i < 2; i++) {
        #pragma unroll
        for (int j = 0; j < 8; j++) {
            #pragma unroll
            for (int r = 0; r < 4; r++) {
                int row = m0 + wm + i * 16 + (lane >> 2) + (r >> 1) * 8;
                int col = n0 + wn + j * 8 + (lane & 3) * 2 + (r & 1);
                float v = acc[i][j][r];
                if (MODE == 0) {
                    C[(size_t)row * ldc + col] = v;
                } else if (MODE == 1) {
                    v += bias[col];
                    v = v / (1.f + expf(-v));
                    C[(size_t)row * ldc + col] = v;
                } else if (MODE == 2) {
                    int b = row >> 10, t = row & 1023;
                    int h = col >> 7,  jj = col & 127;
                    C[(((size_t)(b * HH + h)) * TT + t) * DHD + jj] = v;
                } else if (MODE == 4) {
                    __nv_bfloat16 hv = __float2bfloat16(v);
                    size_t idx = (size_t)row * ldc + col;
                    Chi[idx] = hv;
                    Clo[idx] = __float2bfloat16(v - __bfloat162float(hv));
                } else {  // MODE 5
                    int b = row >> 10, t = row & 1023;
                    int h = col >> 7,  jj = col & 127;
                    size_t idx = (((size_t)(b * HH + h)) * TT + t) * DHD + jj;
                    C[idx] = v;
                    __nv_bfloat16 hv = __float2bfloat16(v);
                    Chi[idx] = hv;
                    Clo[idx] = __float2bfloat16(v - __bfloat162float(hv));
                }
            }
        }
    }
}

// ================= scores = scale * qh @ kh^T (HMMA, causal-skipped) =======
__global__ void __launch_bounds__(256, 1)
scores_mma(const __nv_bfloat16* __restrict__ khhi, const __nv_bfloat16* __restrict__ khlo) {
    extern __shared__ char dsm[];
    const int z  = blockIdx.z;
    const int m0 = blockIdx.y * 128, n0 = blockIdx.x * 128;
    if (n0 > m0 + 127) return;
    const int b = z / HH, h = z % HH;
    const int tid = threadIdx.x;
    const int wid = tid >> 5, lane = tid & 31;
    const int wm  = (wid & 3) * 32;
    const int wn  = (wid >> 2) * 64;
    uint32_t sb = (smem_u32(dsm) + 1023u) & ~1023u;

    // srcs: A = qhi/qlo rows (stride DD), B = khhi/khlo rows (stride DHD)
    const __nv_bfloat16* srcs[4] = {
        g_qhi + ((size_t)(b * TT) + m0) * DD + h * DHD,
        g_qlo + ((size_t)(b * TT) + m0) * DD + h * DHD,
        khhi + (size_t)z * TT * DHD + (size_t)n0 * DHD,
        khlo + (size_t)z * TT * DHD + (size_t)n0 * DHD };
    const int strides[4] = {DD, DD, DHD, DHD};

    #pragma unroll
    for (int buf = 0; buf < 4; buf++) {
        const __nv_bfloat16* src = srcs[buf];
        const int str = strides[buf];
        uint32_t bb = sb + (uint32_t)buf * 32768u;
        #pragma unroll
        for (int it = 0; it < 8; it++) {
            int idx = tid + it * 256;            // 0..2047
            int c = idx >> 10, rem = idx & 1023;
            int m = rem >> 3, j = rem & 7;
            uint32_t saddr = bb + (uint32_t)c * 16384u + (uint32_t)m * 128u
                           + (uint32_t)((j ^ (m & 7)) << 4);
            cpasync16(saddr, src + (size_t)m * str + c * 64 + j * 8);
        }
    }
    CP_COMMIT();
    CP_WAIT(0);
    __syncthreads();

    float acc[2][8][4];
    #pragma unroll
    for (int i = 0; i < 2; i++)
        #pragma unroll
        for (int j = 0; j < 8; j++)
            #pragma unroll
            for (int r = 0; r < 4; r++) acc[i][j][r] = 0.f;

    const int aRow0 = wm + ((lane >> 3) & 1) * 8 + (lane & 7);
    const int aKh   = (lane >> 4) & 1;
    const int bRow0 = wn + ((lane >> 4) & 1) * 8 + (lane & 7);
    const int bKh   = (lane >> 3) & 1;

    #pragma unroll
    for (int c = 0; c < 2; c++) {
        uint32_t cb = (uint32_t)c * 16384u;
        #pragma unroll
        for (int kk = 0; kk < 4; kk++) {
            uint32_t ah[2][4], al[2][4], bh[4][4], bl[4][4];
            #pragma unroll
            for (int mt = 0; mt < 2; mt++) {
                int row = aRow0 + mt * 16;
                int cc = (kk * 2 + aKh) ^ (row & 7);
                uint32_t off = cb + (uint32_t)row * 128u + (uint32_t)cc * 16u;
                ldsm4(ah[mt], sb + off);
                ldsm4(al[mt], sb + 32768u + off);
            }
            #pragma unroll
            for (int g = 0; g < 4; g++) {
                int row = bRow0 + g * 16;
                int cc = (kk * 2 + bKh) ^ (row & 7);
                uint32_t off = cb + (uint32_t)row * 128u + (uint32_t)cc * 16u;
                ldsm4(bh[g], sb + 65536u + off);
                ldsm4(bl[g], sb + 98304u + off);
            }
            #pragma unroll
            for (int i = 0; i < 2; i++)
                #pragma unroll
                for (int j = 0; j < 8; j++) {
                    const uint32_t* bph = &bh[j >> 1][(j & 1) * 2];
                    const uint32_t* bpl = &bl[j >> 1][(j & 1) * 2];
                    mma16816(acc[i][j], ah[i], bph);
                    mma16816(acc[i][j], ah[i], bpl);
                    mma16816(acc[i][j], al[i], bph);
                }
        }
    }

    const float scale = 0.08838834764831845f;
    float* C = g_scores + (size_t)z * TT * TT;
    #pragma unroll
    for (int i = 0; i < 2; i++)
        #pragma unroll
        for (int j = 0; j < 8; j++)
            #pragma unroll
            for (int r = 0; r < 4; r++) {
                int row = m0 + wm + i * 16 + (lane >> 2) + (r >> 1) * 8;
                int col = n0 + wn + j * 8 + (lane & 3) * 2 + (r & 1);
                C[(size_t)row * TT + col] = acc[i][j][r] * scale;
            }
}

// ================= causal row softmax (zero-fill j>i) =================
__global__ void softmax_rows() {
    int g = blockIdx.x;
    int z = g / TT, i = g % TT;
    float* row = g_scores + (size_t)z * TT * TT + (size_t)i * TT;
    int n = i + 1;
    int tid = threadIdx.x;
    __shared__ float sbuf[8];

    float mx = -3.4e38f;
    for (int j = tid; j < n; j += 256) mx = fmaxf(mx, row[j]);
    #pragma unroll
    for (int o = 16; o; o >>= 1) mx = fmaxf(mx, __shfl_xor_sync(0xffffffffu, mx, o));
    if ((tid & 31) == 0) sbuf[tid >> 5] = mx;
    __syncthreads();
    float M = -3.4e38f;
    #pragma unroll
    for (int ww = 0; ww < 8; ww++) M = fmaxf(M, sbuf[ww]);
    __syncthreads();

    float sum = 0.f;
    for (int j = tid; j < n; j += 256) {
        float e = expf(row[j] - M);
        row[j] = e;
        sum += e;
    }
    #pragma unroll
    for (int o = 16; o; o >>= 1) sum += __shfl_xor_sync(0xffffffffu, sum, o);
    if ((tid & 31) == 0) sbuf[tid >> 5] = sum;
    __syncthreads();
    float S = 0.f;
    #pragma unroll
    for (int ww = 0; ww < 8; ww++) S += sbuf[ww];
    float inv = 1.f / S;
    for (int j = tid; j < n; j += 256) row[j] *= inv;
    for (int j = n + tid; j < TT; j += 256) row[j] = 0.f;
}

// ================= O = P @ V (HMMA, in-kernel split, trans-B) ==============
__global__ void __launch_bounds__(256, 1)
pv_mma(const float* __restrict__ vh) {
    extern __shared__ char dsm[];
    const int z  = blockIdx.z;
    const int m0 = blockIdx.y * 128;
    const int b = z / HH, h = z % HH;
    const int tid = threadIdx.x;
    const int wid = tid >> 5, lane = tid & 31;
    const int wm  = (wid & 3) * 32;
    const int wn  = (wid >> 2) * 64;
    uint32_t sb = (smem_u32(dsm) + 1023u) & ~1023u;
    // layout: Phi@0 Plo@16K Vhi@32K Vlo@48K

    const float* P = g_scores + (size_t)z * TT * TT;
    const float* V = vh + (size_t)z * TT * DHD;

    float acc[2][8][4];
    #pragma unroll
    for (int i = 0; i < 2; i++)
        #pragma unroll
        for (int j = 0; j < 8; j++)
            #pragma unroll
            for (int r = 0; r < 4; r++) acc[i][j][r] = 0.f;

    const int aRow0 = wm + ((lane >> 3) & 1) * 8 + (lane & 7);
    const int aKh   = (lane >> 4) & 1;
    const int mi = lane >> 3, p8 = lane & 7;

    const int nch = (m0 >> 6) + 2;
    #pragma unroll 1
    for (int c = 0; c < nch; c++) {
        int k0 = c * 64;
        // stage P: 128 rows x 64k, tasks 1024
        #pragma unroll
        for (int it = 0; it < 4; it++) {
            int idx = tid + it * 256;
            int m = idx >> 3, j = idx & 7;
            const float4* g = (const float4*)(P + (size_t)(m0 + m) * TT + k0 + j * 8);
            uint32_t sa = sb + (uint32_t)m * 128u + (uint32_t)((j ^ (m & 7)) << 4);
            cvt8_sts(sa, sa + 16384u, g[0], g[1]);
        }
        // stage V: 64 k-rows x 128 n, tasks 1024
        #pragma unroll
        for (int it = 0; it < 4; it++) {
            int idx = tid + it * 256;
            int k = idx >> 4, j = idx & 15;
            const float4* g = (const float4*)(V + (size_t)(k0 + k) * DHD + j * 8);
            uint32_t sa = sb + 32768u + (uint32_t)k * 256u + (uint32_t)((j ^ (k & 7)) << 4);
            cvt8_sts(sa, sa + 16384u, g[0], g[1]);
        }
        __syncthreads();

        #pragma unroll
        for (int kk = 0; kk < 4; kk++) {
            uint32_t ah[2][4], al[2][4], bTh[4][4], bTl[4][4];
            #pragma unroll
            for (int mt = 0; mt < 2; mt++) {
                int row = aRow0 + mt * 16;
                int cc = (kk * 2 + aKh) ^ (row & 7);
                uint32_t off = (uint32_t)row * 128u + (uint32_t)cc * 16u;
                ldsm4(ah[mt], sb + off);
                ldsm4(al[mt], sb + 16384u + off);
            }
            int krow = kk * 16 + (mi & 1) * 8 + p8;
            #pragma unroll
            for (int ng = 0; ng < 4; ng++) {
                int nchk = (wn >> 3) + ng * 2 + (mi >> 1);
                uint32_t addr = sb + 32768u + (uint32_t)krow * 256u
                              + (uint32_t)((nchk ^ (krow & 7)) << 4);
                ldsm4t(bTh[ng], addr);
                ldsm4t(bTl[ng], addr + 16384u);
            }
            #pragma unroll
            for (int i = 0; i < 2; i++)
                #pragma unroll
                for (int j = 0; j < 8; j++) {
                    const uint32_t* bph = &bTh[j >> 1][(j & 1) * 2];
                    const uint32_t* bpl = &bTl[j >> 1][(j & 1) * 2];
                    mma16816(acc[i][j], ah[i], bph);
                    mma16816(acc[i][j], ah[i], bpl);
                    mma16816(acc[i][j], al[i], bph);
                }
        }
        __syncthreads();
    }

    // epilogue: attno as bf16 hi/lo at [b*TT+t][h*DHD+col]
    #pragma unroll
    for (int i = 0; i < 2; i++)
        #pragma unroll
        for (int j = 0; j < 8; j++)
            #pragma unroll
            for (int r = 0; r < 4; r++) {
                int t = m0 + wm + i * 16 + (lane >> 2) + (r >> 1) * 8;
                int col = wn + j * 8 + (lane & 3) * 2 + (r & 1);
                float v = acc[i][j][r];
                size_t idx = ((size_t)(b * TT) + t) * DD + h * DHD + col;
                __nv_bfloat16 hv = __float2bfloat16(v);
                g_ahi[idx] = hv;
                g_alo[idx] = __float2bfloat16(v - __bfloat162float(hv));
            }
}

// ================= EMA (chunked parallel scan) =================
__global__ void ema_pass1(const float* __restrict__ x) {
    int idx = blockIdx.x * blockDim.x + threadIdx.x;
    int d = idx % DD;
    int c = (idx / DD) % NC;
    int b = idx / (DD * NC);
    const float beta = 0.9f, om = 1.0f - 0.9f;
    size_t base = ((size_t)b * TT + (size_t)c * LCH) * DD + d;
    float s = 0.f;
    #pragma unroll 4
    for (int p = 0; p < LCH; p++) {
        s = beta * s + om * x[base + (size_t)p * DD];
        g_l2[base + (size_t)p * DD] = s;
    }
    g_fin[c * BD + b * DD + d] = s;
}
__global__ void ema_pass2() {
    int idx = blockIdx.x * blockDim.x + threadIdx.x;
    const float bl = __powf(0.9f, (float)LCH);
    float P = 0.f;
    g_carry[idx] = 0.f;
    for (int c = 1; c < NC; c++) {
        P = g_fin[(c - 1) * BD + idx] + bl * P;
        g_carry[c * BD + idx] = P;
    }
}

// ================= router + level fusion (emit bf16 hi/lo) =================
__global__ void router_fuse(const float* __restrict__ x,
                            const float* __restrict__ l3mem,
                            const float* __restrict__ rw2,
                            const float* __restrict__ rb2,
                            float* __restrict__ lam_out) {
    int r = blockIdx.x;
    int tid = threadIdx.x;
    int b = r / TT, t = r % TT;
    const float* hrow = g_hdn + (size_t)r * DHALF;

    float p0 = 0.f, p1 = 0.f, p2 = 0.f;
    for (int j = tid; j < DHALF; j += 256) {
        float h = hrow[j];
        p0 = fmaf(h, rw2[j], p0);
        p1 = fmaf(h, rw2[DHALF + j], p1);
        p2 = fmaf(h, rw2[2 * DHALF + j], p2);
    }
    #pragma unroll
    for (int o = 16; o; o >>= 1) {
        p0 += __shfl_xor_sync(0xffffffffu, p0, o);
        p1 += __shfl_xor_sync(0xffffffffu, p1, o);
        p2 += __shfl_xor_sync(0xffffffffu, p2, o);
    }
    __shared__ float red0[8], red1[8], red2[8];
    __shared__ float lam[3];
    int lane = tid & 31, w = tid >> 5;
    if (lane == 0) { red0[w] = p0; red1[w] = p1; red2[w] = p2; }
    __syncthreads();
    if (tid == 0) {
        float l0 = rb2[0], l1 = rb2[1], l2v = rb2[2];
        #pragma unroll
        for (int ww = 0; ww < 8; ww++) { l0 += red0[ww]; l1 += red1[ww]; l2v += red2[ww]; }
        float mx = fmaxf(l0, fmaxf(l1, l2v));
        float e0 = expf(l0 - mx), e1 = expf(l1 - mx), e2 = expf(l2v - mx);
        float inv = 1.f / (e0 + e1 + e2);
        lam[0] = e0 * inv; lam[1] = e1 * inv; lam[2] = e2 * inv;
        lam_out[r * 3 + 0] = lam[0];
        lam_out[r * 3 + 1] = lam[1];
        lam_out[r * 3 + 2] = lam[2];
    }
    __syncthreads();
    float la = lam[0], lb = lam[1], lcc = lam[2];

    int c = t / LCH, p = t % LCH;
    float pb = __powf(0.9f, (float)(p + 1));
    const float* carr = g_carry + c * BD + b * DD;
    size_t ro = (size_t)r * DD;
    for (int j = tid; j < DD; j += 256) {
        float l2v = g_l2[ro + j] + pb * carr[j];
        float v = la * x[ro + j] + lb * l2v + lcc * l3mem[b * DD + j];
        __nv_bfloat16 hv = __float2bfloat16(v);
        g_fhi[ro + j] = hv;
        g_flo[ro + j] = __float2bfloat16(v - __bfloat162float(hv));
    }
}

// ================= launch =================
extern "C" void kernel_launch(void* const* d_in, const int* in_sizes, int n_in,
                              void* d_out, int out_size) {
    (void)in_sizes; (void)n_in; (void)out_size;
    const float* x    = (const float*)d_in[0];
    const float* l3m  = (const float*)d_in[1];
    const float* wq   = (const float*)d_in[2];
    const float* wk   = (const float*)d_in[3];
    const float* wv   = (const float*)d_in[4];
    const float* wo   = (const float*)d_in[5];
    const float* rw1  = (const float*)d_in[6];
    const float* rb1  = (const float*)d_in[7];
    const float* rw2  = (const float*)d_in[8];
    const float* rb2  = (const float*)d_in[9];

    float* out     = (float*)d_out;
    float* kh_out  = out + (size_t)RR * DD;
    float* vh_out  = kh_out + (size_t)RR * DD;
    float* lam_out = vh_out + (size_t)RR * DD;

    float* hdn_;
    cudaGetSymbolAddress((void**)&hdn_, g_hdn);

    __nv_bfloat16 *xhi,*xlo,*qhi,*qlo,*fhi,*flo,*ahi,*alo,*khhi,*khlo;
    __nv_bfloat16 *wqh,*wql,*wkh,*wkl,*wvh,*wvl,*woh,*wol,*r1h,*r1l;
    cudaGetSymbolAddress((void**)&xhi, g_xhi);  cudaGetSymbolAddress((void**)&xlo, g_xlo);
    cudaGetSymbolAddress((void**)&qhi, g_qhi);  cudaGetSymbolAddress((void**)&qlo, g_qlo);
    cudaGetSymbolAddress((void**)&fhi, g_fhi);  cudaGetSymbolAddress((void**)&flo, g_flo);
    cudaGetSymbolAddress((void**)&ahi, g_ahi);  cudaGetSymbolAddress((void**)&alo, g_alo);
    cudaGetSymbolAddress((void**)&khhi, g_khhi); cudaGetSymbolAddress((void**)&khlo, g_khlo);
    cudaGetSymbolAddress((void**)&wqh, g_wqhi); cudaGetSymbolAddress((void**)&wql, g_wqlo);
    cudaGetSymbolAddress((void**)&wkh, g_wkhi); cudaGetSymbolAddress((void**)&wkl, g_wklo);
    cudaGetSymbolAddress((void**)&wvh, g_wvhi); cudaGetSymbolAddress((void**)&wvl, g_wvlo);
    cudaGetSymbolAddress((void**)&woh, g_wohi); cudaGetSymbolAddress((void**)&wol, g_wolo);
    cudaGetSymbolAddress((void**)&r1h, g_r1hi); cudaGetSymbolAddress((void**)&r1l, g_r1lo);

    cudaFuncSetAttribute(gemm_mma<0>, cudaFuncAttributeMaxDynamicSharedMemorySize, SMEM_GEMM);
    cudaFuncSetAttribute(gemm_mma<1>, cudaFuncAttributeMaxDynamicSharedMemorySize, SMEM_GEMM);
    cudaFuncSetAttribute(gemm_mma<2>, cudaFuncAttributeMaxDynamicSharedMemorySize, SMEM_GEMM);
    cudaFuncSetAttribute(gemm_mma<4>, cudaFuncAttributeMaxDynamicSharedMemorySize, SMEM_GEMM);
    cudaFuncSetAttribute(gemm_mma<5>, cudaFuncAttributeMaxDynamicSharedMemorySize, SMEM_GEMM);
    cudaFuncSetAttribute(scores_mma, cudaFuncAttributeMaxDynamicSharedMemorySize, SMEM_SCORES);
    cudaFuncSetAttribute(pv_mma,     cudaFuncAttributeMaxDynamicSharedMemorySize, SMEM_PV);

    const int NBIG = RR * DD / 4;
    const int NR1  = DHALF * DD / 4;

    cvt_split<<<NBIG/256, 256>>>((const float4*)x,  (__nv_bfloat162*)xhi, (__nv_bfloat162*)xlo, NBIG);
    cvt_split<<<NBIG/256, 256>>>((const float4*)wq, (__nv_bfloat162*)wqh, (__nv_bfloat162*)wql, NBIG);
    cvt_split<<<NBIG/256, 256>>>((const float4*)wk, (__nv_bfloat162*)wkh, (__nv_bfloat162*)wkl, NBIG);
    cvt_split<<<NBIG/256, 256>>>((const float4*)wv, (__nv_bfloat162*)wvh, (__nv_bfloat162*)wvl, NBIG);
    cvt_split<<<NBIG/256, 256>>>((const float4*)wo, (__nv_bfloat162*)woh, (__nv_bfloat162*)wol, NBIG);
    cvt_split<<<NR1/256,  256>>>((const float4*)rw1,(__nv_bfloat162*)r1h, (__nv_bfloat162*)r1l, NR1);

    ema_pass1<<<BB * NC * DD / 256, 256>>>(x);
    ema_pass2<<<BD / 256, 256>>>();

    // q (bf16 hi/lo direct)
    gemm_mma<4><<<dim3(DD/128, RR/128), 256, SMEM_GEMM>>>(xhi, xlo, wqh, wql, nullptr, qhi, qlo, DD, nullptr);
    // hdn = silu(q @ rw1^T + rb1)
    gemm_mma<1><<<dim3(DHALF/128, RR/128), 256, SMEM_GEMM>>>(qhi, qlo, r1h, r1l, hdn_, nullptr, nullptr, DHALF, rb1);
    // router + fuse (emits fhi/flo)
    router_fuse<<<RR, 256>>>(x, l3m, rw2, rb2, lam_out);
    // K: fp32 out + bf16 hi/lo head layout; V: fp32 out only
    gemm_mma<5><<<dim3(DD/128, RR/128), 256, SMEM_GEMM>>>(fhi, flo, wkh, wkl, kh_out, khhi, khlo, 0, nullptr);
    gemm_mma<2><<<dim3(DD/128, RR/128), 256, SMEM_GEMM>>>(fhi, flo, wvh, wvl, vh_out, nullptr, nullptr, 0, nullptr);
    // attention (HMMA)
    scores_mma<<<dim3(TT/128, TT/128, BB*HH), 256, SMEM_SCORES>>>(khhi, khlo);
    softmax_rows<<<BB*HH*TT, 256>>>();
    pv_mma<<<dim3(1, TT/128, BB*HH), 256, SMEM_PV>>>(vh_out);
    // out = attno @ wo^T
    gemm_mma<0><<<dim3(DD/128, RR/128), 256, SMEM_GEMM>>>(ahi, alo, woh, wol, out, nullptr, nullptr, DD, nullptr);
}

// round 6
// speedup vs baseline: 3.1201x; 1.1515x over previous
#include <cuda_runtime.h>
#include <cuda_bf16.h>
#include <math.h>
#include <stdint.h>

// Problem constants
#define BB 2
#define TT 1024
#define DD 2048
#define HH 16
#define DHD 128
#define RR (BB*TT)       // 2048
#define DHALF (DD/2)     // 1024
#define LCH 128
#define NC (TT/LCH)
#define BD (BB*DD)

#define KDIM 2048
#define NCHUNK (KDIM/64)
#define STAGE_BYTES 65536
#define SMEM_GEMM (2*STAGE_BYTES + 1024)
#define SMEM_FLASH (65536 + 2*65536 + 1024)   // Q + 2 KV stages

// -------- fp32 scratch --------
__device__ float g_hdn[RR*DHALF];
__device__ float g_l2[RR*DD];
__device__ float g_fin[NC*BD];
__device__ float g_carry[NC*BD];

// -------- bf16 hi/lo scratch --------
__device__ __nv_bfloat16 g_xhi[RR*DD],  g_xlo[RR*DD];
__device__ __nv_bfloat16 g_qhi[RR*DD],  g_qlo[RR*DD];
__device__ __nv_bfloat16 g_fhi[RR*DD],  g_flo[RR*DD];
__device__ __nv_bfloat16 g_ahi[RR*DD],  g_alo[RR*DD];
__device__ __nv_bfloat16 g_khhi[RR*DD], g_khlo[RR*DD];   // [b,h,t,dh]
__device__ __nv_bfloat16 g_vhhi[RR*DD], g_vhlo[RR*DD];   // [b,h,t,dh]
__device__ __nv_bfloat16 g_wqhi[DD*DD], g_wqlo[DD*DD];
__device__ __nv_bfloat16 g_wkhi[DD*DD], g_wklo[DD*DD];
__device__ __nv_bfloat16 g_wvhi[DD*DD], g_wvlo[DD*DD];
__device__ __nv_bfloat16 g_wohi[DD*DD], g_wolo[DD*DD];
__device__ __nv_bfloat16 g_r1hi[DHALF*DD], g_r1lo[DHALF*DD];

// ================= PTX helpers =================
__device__ __forceinline__ uint32_t smem_u32(const void* p) {
    uint32_t a;
    asm("{ .reg .u64 t; cvta.to.shared.u64 t, %1; cvt.u32.u64 %0, t; }" : "=r"(a) : "l"(p));
    return a;
}
__device__ __forceinline__ void cpasync16(uint32_t s, const void* g) {
    asm volatile("cp.async.cg.shared.global [%0], [%1], 16;" :: "r"(s), "l"(g));
}
#define CP_COMMIT() asm volatile("cp.async.commit_group;" ::: "memory")
#define CP_WAIT(n)  asm volatile("cp.async.wait_group %0;" :: "n"(n) : "memory")

__device__ __forceinline__ void ldsm4(uint32_t* r, uint32_t addr) {
    asm volatile("ldmatrix.sync.aligned.m8n8.x4.shared.b16 {%0,%1,%2,%3}, [%4];"
        : "=r"(r[0]), "=r"(r[1]), "=r"(r[2]), "=r"(r[3]) : "r"(addr));
}
__device__ __forceinline__ void ldsm4t(uint32_t* r, uint32_t addr) {
    asm volatile("ldmatrix.sync.aligned.m8n8.x4.trans.shared.b16 {%0,%1,%2,%3}, [%4];"
        : "=r"(r[0]), "=r"(r[1]), "=r"(r[2]), "=r"(r[3]) : "r"(addr));
}
__device__ __forceinline__ void mma16816(float* c, const uint32_t* a, const uint32_t* b) {
    asm volatile(
        "mma.sync.aligned.m16n8k16.row.col.f32.bf16.bf16.f32 "
        "{%0,%1,%2,%3}, {%4,%5,%6,%7}, {%8,%9}, {%0,%1,%2,%3};"
        : "+f"(c[0]), "+f"(c[1]), "+f"(c[2]), "+f"(c[3])
        : "r"(a[0]), "r"(a[1]), "r"(a[2]), "r"(a[3]), "r"(b[0]), "r"(b[1]));
}
__device__ __forceinline__ void pack_hilo(float x, float y, uint32_t& hi, uint32_t& lo) {
    __nv_bfloat16 hx = __float2bfloat16(x), hy = __float2bfloat16(y);
    __nv_bfloat16 lx = __float2bfloat16(x - __bfloat162float(hx));
    __nv_bfloat16 ly = __float2bfloat16(y - __bfloat162float(hy));
    __nv_bfloat162 hp(hx, hy), lp(lx, ly);
    hi = *(uint32_t*)&hp; lo = *(uint32_t*)&lp;
}

// ================= fp32 -> bf16 hi/lo split =================
__global__ void cvt_split(const float4* __restrict__ src,
                          __nv_bfloat162* __restrict__ hi,
                          __nv_bfloat162* __restrict__ lo, int n4) {
    int i = blockIdx.x * blockDim.x + threadIdx.x;
    if (i >= n4) return;
    float4 v = src[i];
    __nv_bfloat16 h0 = __float2bfloat16(v.x), h1 = __float2bfloat16(v.y);
    __nv_bfloat16 h2 = __float2bfloat16(v.z), h3 = __float2bfloat16(v.w);
    __nv_bfloat16 l0 = __float2bfloat16(v.x - __bfloat162float(h0));
    __nv_bfloat16 l1 = __float2bfloat16(v.y - __bfloat162float(h1));
    __nv_bfloat16 l2 = __float2bfloat16(v.z - __bfloat162float(h2));
    __nv_bfloat16 l3 = __float2bfloat16(v.w - __bfloat162float(h3));
    hi[2*i]   = __nv_bfloat162(h0, h1);
    hi[2*i+1] = __nv_bfloat162(h2, h3);
    lo[2*i]   = __nv_bfloat162(l0, l1);
    lo[2*i+1] = __nv_bfloat162(l2, l3);
}

// ================= HMMA GEMM: C = A * B^T (split bf16, fp32 acc) ===========
// MODE 0: fp32 plain   MODE 1: bias+silu fp32
// MODE 4: bf16 hi/lo plain   MODE 5: fp32 scatter + bf16 hi/lo scatter [b,h,t,dh]
template<int MODE>
__global__ void __launch_bounds__(256, 1)
gemm_mma(const __nv_bfloat16* __restrict__ Ahi, const __nv_bfloat16* __restrict__ Alo,
         const __nv_bfloat16* __restrict__ Bhi, const __nv_bfloat16* __restrict__ Blo,
         float* __restrict__ C, __nv_bfloat16* __restrict__ Chi,
         __nv_bfloat16* __restrict__ Clo, int ldc, const float* __restrict__ bias) {
    extern __shared__ char dsm[];
    const int tid  = threadIdx.x;
    const int wid  = tid >> 5, lane = tid & 31;
    const int m0   = blockIdx.y * 128, n0 = blockIdx.x * 128;
    const int wm   = (wid & 3) * 32;
    const int wn   = (wid >> 2) * 64;
    uint32_t sb = (smem_u32(dsm) + 1023u) & ~1023u;

    const __nv_bfloat16* gsrc[4] = {
        Ahi + (size_t)m0 * KDIM, Alo + (size_t)m0 * KDIM,
        Bhi + (size_t)n0 * KDIM, Blo + (size_t)n0 * KDIM };

    auto load_stage = [&](int s, int k0) {
        uint32_t base = sb + (uint32_t)s * STAGE_BYTES;
        #pragma unroll
        for (int tI = 0; tI < 4; tI++) {
            uint32_t tb = base + (uint32_t)tI * 16384u;
            const char* g = (const char*)(gsrc[tI] + k0);
            #pragma unroll
            for (int it = 0; it < 4; it++) {
                int idx = tid + it * 256;
                int m = idx >> 3, j = idx & 7;
                uint32_t saddr = tb + (uint32_t)m * 128u + (uint32_t)((j ^ (m & 7)) << 4);
                cpasync16(saddr, g + (size_t)m * (KDIM * 2) + j * 16);
            }
        }
        CP_COMMIT();
    };

    float acc[2][8][4];
    #pragma unroll
    for (int i = 0; i < 2; i++)
        #pragma unroll
        for (int j = 0; j < 8; j++)
            #pragma unroll
            for (int r = 0; r < 4; r++) acc[i][j][r] = 0.f;

    const int aRow0 = wm + ((lane >> 3) & 1) * 8 + (lane & 7);
    const int aKh   = (lane >> 4) & 1;
    const int bRow0 = wn + ((lane >> 4) & 1) * 8 + (lane & 7);
    const int bKh   = (lane >> 3) & 1;

    load_stage(0, 0);
    load_stage(1, 64);

    #pragma unroll 1
    for (int c = 0; c < NCHUNK; c++) {
        if (c + 2 < NCHUNK) { CP_WAIT(1); } else { CP_WAIT(0); }
        __syncthreads();

        uint32_t base = sb + (uint32_t)(c & 1) * STAGE_BYTES;
        #pragma unroll
        for (int kk = 0; kk < 4; kk++) {
            uint32_t ah[2][4], al[2][4], bh[4][4], bl[4][4];
            #pragma unroll
            for (int mt = 0; mt < 2; mt++) {
                int row = aRow0 + mt * 16;
                int cc = (kk * 2 + aKh) ^ (row & 7);
                uint32_t off = (uint32_t)row * 128u + (uint32_t)cc * 16u;
                ldsm4(ah[mt], base + off);
                ldsm4(al[mt], base + 16384u + off);
            }
            #pragma unroll
            for (int g = 0; g < 4; g++) {
                int row = bRow0 + g * 16;
                int cc = (kk * 2 + bKh) ^ (row & 7);
                uint32_t off = (uint32_t)row * 128u + (uint32_t)cc * 16u;
                ldsm4(bh[g], base + 32768u + off);
                ldsm4(bl[g], base + 49152u + off);
            }
            #pragma unroll
            for (int i = 0; i < 2; i++)
                #pragma unroll
                for (int j = 0; j < 8; j++) {
                    const uint32_t* bph = &bh[j >> 1][(j & 1) * 2];
                    const uint32_t* bpl = &bl[j >> 1][(j & 1) * 2];
                    mma16816(acc[i][j], ah[i], bph);
                    mma16816(acc[i][j], ah[i], bpl);
                    mma16816(acc[i][j], al[i], bph);
                }
        }
        __syncthreads();
        if (c + 2 < NCHUNK) load_stage(c & 1, (c + 2) * 64);
    }

    #pragma unroll
    for (int i = 0; i < 2; i++) {
        #pragma unroll
        for (int j = 0; j < 8; j++) {
            #pragma unroll
            for (int r = 0; r < 4; r++) {
                int row = m0 + wm + i * 16 + (lane >> 2) + (r >> 1) * 8;
                int col = n0 + wn + j * 8 + (lane & 3) * 2 + (r & 1);
                float v = acc[i][j][r];
                if (MODE == 0) {
                    C[(size_t)row * ldc + col] = v;
                } else if (MODE == 1) {
                    v += bias[col];
                    v = v / (1.f + expf(-v));
                    C[(size_t)row * ldc + col] = v;
                } else if (MODE == 4) {
                    __nv_bfloat16 hv = __float2bfloat16(v);
                    size_t idx = (size_t)row * ldc + col;
                    Chi[idx] = hv;
                    Clo[idx] = __float2bfloat16(v - __bfloat162float(hv));
                } else {  // MODE 5
                    int b = row >> 10, t = row & 1023;
                    int h = col >> 7,  jj = col & 127;
                    size_t idx = (((size_t)(b * HH + h)) * TT + t) * DHD + jj;
                    C[idx] = v;
                    __nv_bfloat16 hv = __float2bfloat16(v);
                    Chi[idx] = hv;
                    Clo[idx] = __float2bfloat16(v - __bfloat162float(hv));
                }
            }
        }
    }
}

// ================= flash attention (fused S, softmax, PV) ==================
// grid (BH=32, 8), qi reversed so longest CTAs schedule first.
// 8 warps x m16 q rows. kv chunks of 64, double-buffered cp.async.
__global__ void __launch_bounds__(256, 1)
flash_attn(const __nv_bfloat16* __restrict__ khhi, const __nv_bfloat16* __restrict__ khlo,
           const __nv_bfloat16* __restrict__ vhhi, const __nv_bfloat16* __restrict__ vhlo) {
    extern __shared__ char dsm[];
    const int z  = blockIdx.x;                  // b*H + h
    const int qi = (int)gridDim.y - 1 - (int)blockIdx.y;
    const int b = z >> 4, h = z & 15;
    const int m0 = qi * 128;
    const int tid = threadIdx.x, wid = tid >> 5, lane = tid & 31;
    uint32_t sb = (smem_u32(dsm) + 1023u) & ~1023u;
    const uint32_t qs = sb;                     // Q hi @0, Q lo @32768

    // ---- load Q tile (128 rows x 256B, hi+lo), group 0
    {
        const __nv_bfloat16* Qh = g_qhi + ((size_t)(b * TT) + m0) * DD + h * DHD;
        const __nv_bfloat16* Ql = g_qlo + ((size_t)(b * TT) + m0) * DD + h * DHD;
        #pragma unroll
        for (int it = 0; it < 8; it++) {
            int idx = tid + it * 256;
            int row = idx >> 4, u = idx & 15;
            uint32_t sa = qs + (uint32_t)row * 256u + (uint32_t)((u ^ (row & 7)) << 4);
            cpasync16(sa,           Qh + (size_t)row * DD + u * 8);
            cpasync16(sa + 32768u,  Ql + (size_t)row * DD + u * 8);
        }
    }
    const __nv_bfloat16* Kh = khhi + (size_t)z * TT * DHD;
    const __nv_bfloat16* Kl = khlo + (size_t)z * TT * DHD;
    const __nv_bfloat16* Vh = vhhi + (size_t)z * TT * DHD;
    const __nv_bfloat16* Vl = vhlo + (size_t)z * TT * DHD;

    // stage layout: Khi@0 Klo@16K Vhi@32K Vlo@48K (64 rows x 256B each)
    auto load_kv = [&](int s, int ch) {
        uint32_t base = sb + 65536u + (uint32_t)s * 65536u;
        const __nv_bfloat16* srcs[4] = {
            Kh + (size_t)ch * 64 * DHD, Kl + (size_t)ch * 64 * DHD,
            Vh + (size_t)ch * 64 * DHD, Vl + (size_t)ch * 64 * DHD };
        #pragma unroll
        for (int tI = 0; tI < 4; tI++) {
            uint32_t tb = base + (uint32_t)tI * 16384u;
            const __nv_bfloat16* g = srcs[tI];
            #pragma unroll
            for (int it = 0; it < 4; it++) {
                int idx = tid + it * 256;
                int row = idx >> 4, u = idx & 15;
                cpasync16(tb + (uint32_t)row * 256u + (uint32_t)((u ^ (row & 7)) << 4),
                          g + (size_t)row * DHD + u * 8);
            }
        }
        CP_COMMIT();
    };

    const int nch = 2 * qi + 2;
    load_kv(0, 0);

    float m_[2] = {-1e30f, -1e30f}, l_[2] = {0.f, 0.f};
    float oacc[16][4];
    #pragma unroll
    for (int j = 0; j < 16; j++)
        #pragma unroll
        for (int r = 0; r < 4; r++) oacc[j][r] = 0.f;

    const int qrow_lo = wid * 16 + (lane >> 2);     // local q row (and +8)
    const float scale = 0.08838834764831845f;

    #pragma unroll 1
    for (int ch = 0; ch < nch; ch++) {
        if (ch + 1 < nch) {
            load_kv((ch + 1) & 1, ch + 1);
            CP_WAIT(1);
        } else {
            CP_WAIT(0);
        }
        __syncthreads();
        uint32_t kb = sb + 65536u + (uint32_t)(ch & 1) * 65536u;
        uint32_t vb = kb + 32768u;

        // ---- S = Q K^T : m16 x n64 x k128 (3-product split)
        float sacc[8][4];
        #pragma unroll
        for (int j = 0; j < 8; j++)
            #pragma unroll
            for (int r = 0; r < 4; r++) sacc[j][r] = 0.f;

        #pragma unroll
        for (int kk = 0; kk < 8; kk++) {
            uint32_t ah[4], al[4];
            int arow = wid * 16 + ((lane >> 3) & 1) * 8 + (lane & 7);
            int au = (kk * 2 + ((lane >> 4) & 1)) ^ (arow & 7);
            uint32_t aoff = (uint32_t)arow * 256u + (uint32_t)au * 16u;
            ldsm4(ah, qs + aoff);
            ldsm4(al, qs + 32768u + aoff);
            #pragma unroll
            for (int g = 0; g < 4; g++) {
                uint32_t bh_[4], bl_[4];
                int brow = g * 16 + ((lane >> 4) & 1) * 8 + (lane & 7);
                int bu = (kk * 2 + ((lane >> 3) & 1)) ^ (brow & 7);
                uint32_t boff = (uint32_t)brow * 256u + (uint32_t)bu * 16u;
                ldsm4(bh_, kb + boff);
                ldsm4(bl_, kb + 16384u + boff);
                #pragma unroll
                for (int jj = 0; jj < 2; jj++) {
                    int j = g * 2 + jj;
                    mma16816(sacc[j], ah, &bh_[jj * 2]);
                    mma16816(sacc[j], ah, &bl_[jj * 2]);
                    mma16816(sacc[j], al, &bh_[jj * 2]);
                }
            }
        }

        // ---- mask + online softmax
        const int kvbase = ch * 64;
        const bool maskp = (kvbase + 63 > m0);
        float mx[2] = {-1e30f, -1e30f};
        #pragma unroll
        for (int j = 0; j < 8; j++)
            #pragma unroll
            for (int r = 0; r < 4; r++) {
                float v = sacc[j][r] * scale;
                if (maskp) {
                    int col_g = kvbase + 8 * j + 2 * (lane & 3) + (r & 1);
                    int row_g = m0 + qrow_lo + (r >> 1) * 8;
                    if (col_g > row_g) v = -1e30f;
                }
                sacc[j][r] = v;
                mx[r >> 1] = fmaxf(mx[r >> 1], v);
            }
        #pragma unroll
        for (int rr = 0; rr < 2; rr++) {
            mx[rr] = fmaxf(mx[rr], __shfl_xor_sync(0xffffffffu, mx[rr], 1));
            mx[rr] = fmaxf(mx[rr], __shfl_xor_sync(0xffffffffu, mx[rr], 2));
        }
        float mn0 = fmaxf(m_[0], mx[0]), mn1 = fmaxf(m_[1], mx[1]);
        float al0 = __expf(m_[0] - mn0), al1 = __expf(m_[1] - mn1);
        float rs[2] = {0.f, 0.f};
        #pragma unroll
        for (int j = 0; j < 8; j++)
            #pragma unroll
            for (int r = 0; r < 4; r++) {
                float p = __expf(sacc[j][r] - ((r >> 1) ? mn1 : mn0));
                sacc[j][r] = p;
                rs[r >> 1] += p;
            }
        #pragma unroll
        for (int rr = 0; rr < 2; rr++) {
            rs[rr] += __shfl_xor_sync(0xffffffffu, rs[rr], 1);
            rs[rr] += __shfl_xor_sync(0xffffffffu, rs[rr], 2);
        }
        l_[0] = l_[0] * al0 + rs[0];
        l_[1] = l_[1] * al1 + rs[1];
        m_[0] = mn0; m_[1] = mn1;
        #pragma unroll
        for (int j = 0; j < 16; j++) {
            oacc[j][0] *= al0; oacc[j][1] *= al0;
            oacc[j][2] *= al1; oacc[j][3] *= al1;
        }

        // ---- O += P V : m16 x n128 x k64 (P split in-register)
        #pragma unroll
        for (int kk = 0; kk < 4; kk++) {
            uint32_t aph[4], apl[4];
            pack_hilo(sacc[2*kk][0],   sacc[2*kk][1],   aph[0], apl[0]);
            pack_hilo(sacc[2*kk][2],   sacc[2*kk][3],   aph[1], apl[1]);
            pack_hilo(sacc[2*kk+1][0], sacc[2*kk+1][1], aph[2], apl[2]);
            pack_hilo(sacc[2*kk+1][2], sacc[2*kk+1][3], aph[3], apl[3]);
            int krow = kk * 16 + ((lane >> 3) & 1) * 8 + (lane & 7);
            #pragma unroll
            for (int ng = 0; ng < 8; ng++) {
                int nchk = ng * 2 + (lane >> 4);
                uint32_t addr = vb + (uint32_t)krow * 256u
                              + (uint32_t)((nchk ^ (krow & 7)) << 4);
                uint32_t bvh[4], bvl[4];
                ldsm4t(bvh, addr);
                ldsm4t(bvl, addr + 16384u);
                #pragma unroll
                for (int jj = 0; jj < 2; jj++) {
                    int j = ng * 2 + jj;
                    mma16816(oacc[j], aph, &bvh[jj * 2]);
                    mma16816(oacc[j], aph, &bvl[jj * 2]);
                    mma16816(oacc[j], apl, &bvh[jj * 2]);
                }
            }
        }
        __syncthreads();
    }

    // ---- epilogue: O/l, split hi/lo -> g_ahi/g_alo at [b,t,d]
    float inv0 = 1.f / l_[0], inv1 = 1.f / l_[1];
    #pragma unroll
    for (int j = 0; j < 16; j++)
        #pragma unroll
        for (int r = 0; r < 4; r++) {
            int t = m0 + qrow_lo + (r >> 1) * 8;
            int col = 8 * j + 2 * (lane & 3) + (r & 1);
            float v = oacc[j][r] * ((r >> 1) ? inv1 : inv0);
            size_t idx = ((size_t)(b * TT) + t) * DD + h * DHD + col;
            __nv_bfloat16 hv = __float2bfloat16(v);
            g_ahi[idx] = hv;
            g_alo[idx] = __float2bfloat16(v - __bfloat162float(hv));
        }
}

// ================= EMA (chunked parallel scan) =================
__global__ void ema_pass1(const float* __restrict__ x) {
    int idx = blockIdx.x * blockDim.x + threadIdx.x;
    int d = idx % DD;
    int c = (idx / DD) % NC;
    int b = idx / (DD * NC);
    const float beta = 0.9f, om = 1.0f - 0.9f;
    size_t base = ((size_t)b * TT + (size_t)c * LCH) * DD + d;
    float s = 0.f;
    #pragma unroll 4
    for (int p = 0; p < LCH; p++) {
        s = beta * s + om * x[base + (size_t)p * DD];
        g_l2[base + (size_t)p * DD] = s;
    }
    g_fin[c * BD + b * DD + d] = s;
}
__global__ void ema_pass2() {
    int idx = blockIdx.x * blockDim.x + threadIdx.x;
    const float bl = __powf(0.9f, (float)LCH);
    float P = 0.f;
    g_carry[idx] = 0.f;
    for (int c = 1; c < NC; c++) {
        P = g_fin[(c - 1) * BD + idx] + bl * P;
        g_carry[c * BD + idx] = P;
    }
}

// ================= router + level fusion (emit bf16 hi/lo) =================
__global__ void router_fuse(const float* __restrict__ x,
                            const float* __restrict__ l3mem,
                            const float* __restrict__ rw2,
                            const float* __restrict__ rb2,
                            float* __restrict__ lam_out) {
    int r = blockIdx.x;
    int tid = threadIdx.x;
    int b = r / TT, t = r % TT;
    const float* hrow = g_hdn + (size_t)r * DHALF;

    float p0 = 0.f, p1 = 0.f, p2 = 0.f;
    for (int j = tid; j < DHALF; j += 256) {
        float h = hrow[j];
        p0 = fmaf(h, rw2[j], p0);
        p1 = fmaf(h, rw2[DHALF + j], p1);
        p2 = fmaf(h, rw2[2 * DHALF + j], p2);
    }
    #pragma unroll
    for (int o = 16; o; o >>= 1) {
        p0 += __shfl_xor_sync(0xffffffffu, p0, o);
        p1 += __shfl_xor_sync(0xffffffffu, p1, o);
        p2 += __shfl_xor_sync(0xffffffffu, p2, o);
    }
    __shared__ float red0[8], red1[8], red2[8];
    __shared__ float lam[3];
    int lane = tid & 31, w = tid >> 5;
    if (lane == 0) { red0[w] = p0; red1[w] = p1; red2[w] = p2; }
    __syncthreads();
    if (tid == 0) {
        float l0 = rb2[0], l1 = rb2[1], l2v = rb2[2];
        #pragma unroll
        for (int ww = 0; ww < 8; ww++) { l0 += red0[ww]; l1 += red1[ww]; l2v += red2[ww]; }
        float mx = fmaxf(l0, fmaxf(l1, l2v));
        float e0 = expf(l0 - mx), e1 = expf(l1 - mx), e2 = expf(l2v - mx);
        float inv = 1.f / (e0 + e1 + e2);
        lam[0] = e0 * inv; lam[1] = e1 * inv; lam[2] = e2 * inv;
        lam_out[r * 3 + 0] = lam[0];
        lam_out[r * 3 + 1] = lam[1];
        lam_out[r * 3 + 2] = lam[2];
    }
    __syncthreads();
    float la = lam[0], lb = lam[1], lcc = lam[2];

    int c = t / LCH, p = t % LCH;
    float pb = __powf(0.9f, (float)(p + 1));
    const float* carr = g_carry + c * BD + b * DD;
    size_t ro = (size_t)r * DD;
    for (int j = tid; j < DD; j += 256) {
        float l2v = g_l2[ro + j] + pb * carr[j];
        float v = la * x[ro + j] + lb * l2v + lcc * l3mem[b * DD + j];
        __nv_bfloat16 hv = __float2bfloat16(v);
        g_fhi[ro + j] = hv;
        g_flo[ro + j] = __float2bfloat16(v - __bfloat162float(hv));
    }
}

// ================= launch =================
extern "C" void kernel_launch(void* const* d_in, const int* in_sizes, int n_in,
                              void* d_out, int out_size) {
    (void)in_sizes; (void)n_in; (void)out_size;
    const float* x    = (const float*)d_in[0];
    const float* l3m  = (const float*)d_in[1];
    const float* wq   = (const float*)d_in[2];
    const float* wk   = (const float*)d_in[3];
    const float* wv   = (const float*)d_in[4];
    const float* wo   = (const float*)d_in[5];
    const float* rw1  = (const float*)d_in[6];
    const float* rb1  = (const float*)d_in[7];
    const float* rw2  = (const float*)d_in[8];
    const float* rb2  = (const float*)d_in[9];

    float* out     = (float*)d_out;
    float* kh_out  = out + (size_t)RR * DD;
    float* vh_out  = kh_out + (size_t)RR * DD;
    float* lam_out = vh_out + (size_t)RR * DD;

    float* hdn_;
    cudaGetSymbolAddress((void**)&hdn_, g_hdn);

    __nv_bfloat16 *xhi,*xlo,*qhi,*qlo,*fhi,*flo,*ahi,*alo,*khhi,*khlo,*vhhi,*vhlo;
    __nv_bfloat16 *wqh,*wql,*wkh,*wkl,*wvh,*wvl,*woh,*wol,*r1h,*r1l;
    cudaGetSymbolAddress((void**)&xhi, g_xhi);  cudaGetSymbolAddress((void**)&xlo, g_xlo);
    cudaGetSymbolAddress((void**)&qhi, g_qhi);  cudaGetSymbolAddress((void**)&qlo, g_qlo);
    cudaGetSymbolAddress((void**)&fhi, g_fhi);  cudaGetSymbolAddress((void**)&flo, g_flo);
    cudaGetSymbolAddress((void**)&ahi, g_ahi);  cudaGetSymbolAddress((void**)&alo, g_alo);
    cudaGetSymbolAddress((void**)&khhi, g_khhi); cudaGetSymbolAddress((void**)&khlo, g_khlo);
    cudaGetSymbolAddress((void**)&vhhi, g_vhhi); cudaGetSymbolAddress((void**)&vhlo, g_vhlo);
    cudaGetSymbolAddress((void**)&wqh, g_wqhi); cudaGetSymbolAddress((void**)&wql, g_wqlo);
    cudaGetSymbolAddress((void**)&wkh, g_wkhi); cudaGetSymbolAddress((void**)&wkl, g_wklo);
    cudaGetSymbolAddress((void**)&wvh, g_wvhi); cudaGetSymbolAddress((void**)&wvl, g_wvlo);
    cudaGetSymbolAddress((void**)&woh, g_wohi); cudaGetSymbolAddress((void**)&wol, g_wolo);
    cudaGetSymbolAddress((void**)&r1h, g_r1hi); cudaGetSymbolAddress((void**)&r1l, g_r1lo);

    cudaFuncSetAttribute(gemm_mma<0>, cudaFuncAttributeMaxDynamicSharedMemorySize, SMEM_GEMM);
    cudaFuncSetAttribute(gemm_mma<1>, cudaFuncAttributeMaxDynamicSharedMemorySize, SMEM_GEMM);
    cudaFuncSetAttribute(gemm_mma<4>, cudaFuncAttributeMaxDynamicSharedMemorySize, SMEM_GEMM);
    cudaFuncSetAttribute(gemm_mma<5>, cudaFuncAttributeMaxDynamicSharedMemorySize, SMEM_GEMM);
    cudaFuncSetAttribute(flash_attn,  cudaFuncAttributeMaxDynamicSharedMemorySize, SMEM_FLASH);

    const int NBIG = RR * DD / 4;
    const int NR1  = DHALF * DD / 4;

    cvt_split<<<NBIG/256, 256>>>((const float4*)x,  (__nv_bfloat162*)xhi, (__nv_bfloat162*)xlo, NBIG);
    cvt_split<<<NBIG/256, 256>>>((const float4*)wq, (__nv_bfloat162*)wqh, (__nv_bfloat162*)wql, NBIG);
    cvt_split<<<NBIG/256, 256>>>((const float4*)wk, (__nv_bfloat162*)wkh, (__nv_bfloat162*)wkl, NBIG);
    cvt_split<<<NBIG/256, 256>>>((const float4*)wv, (__nv_bfloat162*)wvh, (__nv_bfloat162*)wvl, NBIG);
    cvt_split<<<NBIG/256, 256>>>((const float4*)wo, (__nv_bfloat162*)woh, (__nv_bfloat162*)wol, NBIG);
    cvt_split<<<NR1/256,  256>>>((const float4*)rw1,(__nv_bfloat162*)r1h, (__nv_bfloat162*)r1l, NR1);

    ema_pass1<<<BB * NC * DD / 256, 256>>>(x);
    ema_pass2<<<BD / 256, 256>>>();

    // q (bf16 hi/lo direct)
    gemm_mma<4><<<dim3(DD/128, RR/128), 256, SMEM_GEMM>>>(xhi, xlo, wqh, wql, nullptr, qhi, qlo, DD, nullptr);
    // hdn = silu(q @ rw1^T + rb1)
    gemm_mma<1><<<dim3(DHALF/128, RR/128), 256, SMEM_GEMM>>>(qhi, qlo, r1h, r1l, hdn_, nullptr, nullptr, DHALF, rb1);
    // router + fuse (emits fhi/flo)
    router_fuse<<<RR, 256>>>(x, l3m, rw2, rb2, lam_out);
    // K/V: fp32 head-layout outputs + bf16 hi/lo head layout
    gemm_mma<5><<<dim3(DD/128, RR/128), 256, SMEM_GEMM>>>(fhi, flo, wkh, wkl, kh_out, khhi, khlo, 0, nullptr);
    gemm_mma<5><<<dim3(DD/128, RR/128), 256, SMEM_GEMM>>>(fhi, flo, wvh, wvl, vh_out, vhhi, vhlo, 0, nullptr);
    // fused attention
    flash_attn<<<dim3(BB*HH, TT/128), 256, SMEM_FLASH>>>(khhi, khlo, vhhi, vhlo);
    // out = attno @ wo^T
    gemm_mma<0><<<dim3(DD/128, RR/128), 256, SMEM_GEMM>>>(ahi, alo, woh, wol, out, nullptr, nullptr, DD, nullptr);
}